// round 1
// baseline (speedup 1.0000x reference)
#include <cuda_runtime.h>
#include <math.h>

#define Bn   8
#define Hn   512
#define Wn   512
#define HWn  (Hn*Wn)      // 262144 = 2^18
#define BHWn (Bn*HWn)     // 2097152
#define NCH  24           // B*3 channels for percentile

// ---------------- scratch (static device globals; no allocation) ----------------
__device__ float  g_t0[BHWn];
__device__ float  g_gray[BHWn];
__device__ float  g_tg[BHWn];
__device__ float4 g_i4[BHWn];    // H-pass sums of (gray, tg, gray*tg, gray*gray)
__device__ float2 g_ab[BHWn];    // (a, b) guided filter coefficients
__device__ float2 g_i2[BHWn];    // H-pass sums of (a, b)
__device__ unsigned int g_h1[NCH*4096];
__device__ unsigned int g_h2[NCH*2*256];
__device__ unsigned int g_h3[NCH*2*1024];
__device__ int   g_t1[NCH*2];
__device__ int   g_r1[NCH*2];
__device__ int   g_t22[NCH*2];
__device__ int   g_r2[NCH*2];
__device__ float g_pl[NCH];
__device__ float g_ph[NCH];

__device__ __forceinline__ int reflecti(int i, int n) {
    if (i < 0) i = -i;
    if (i > n - 1) i = 2 * (n - 1) - i;
    return i;
}
__device__ __forceinline__ int clamp_r(int r) {
    if (r < 1) r = 1;
    if (r > 50) r = 50;
    return r;
}

// ---------------- K1: t0 + gray ----------------
__global__ void k_pre(const float* __restrict__ img,
                      const float* __restrict__ omega,
                      const float* __restrict__ A) {
    int i = blockIdx.x * blockDim.x + threadIdx.x;
    if (i >= BHWn) return;
    int b = i >> 18;
    int p = i & (HWn - 1);
    float r  = img[(b*3+0)*HWn + p];
    float g  = img[(b*3+1)*HWn + p];
    float bl = img[(b*3+2)*HWn + p];
    float a0 = A[b*3+0] + 1e-8f;
    float a1 = A[b*3+1] + 1e-8f;
    float a2 = A[b*3+2] + 1e-8f;
    float dark = fminf(fminf(r / a0, g / a1), bl / a2);
    g_t0[i]   = 1.0f - omega[b] * dark;
    g_gray[i] = 0.299f * r + 0.587f * g + 0.114f * bl;
}

// ---------------- K2: gradient-constrained tg ----------------
__global__ void k_tg() {
    int i = blockIdx.x * blockDim.x + threadIdx.x;
    if (i >= BHWn) return;
    int b = i >> 18;
    int p = i & (HWn - 1);
    int y = p >> 9;
    int x = p & (Wn - 1);
    const float* t0 = g_t0 + b * HWn;
    int ys = (y == 0) ? 0 : y - 1;
    float tys_x = t0[ys * Wn + x];
    float txv;
    if (x == 0) {
        txv = t0[ys * Wn];
    } else {
        float tprev = t0[ys * Wn + x - 1];
        txv = tprev * expf(-fabsf(tys_x - tprev));
    }
    float tgv;
    if (y == 0) {
        tgv = txv;
    } else {
        float tcur = t0[y * Wn + x];
        tgv = txv * expf(-fabsf(tcur - tys_x));
    }
    g_tg[i] = tgv;
}

// ---------------- K3: horizontal box (4 planes at once), prefix-sum per row ----------------
__global__ void k_hbox4(const int* __restrict__ rp) {
    int r = clamp_r(rp[0]);
    __shared__ float4 P[Wn + 1];
    __shared__ float4 wsh[16];
    int x = threadIdx.x;               // 512 threads
    int rowbase = blockIdx.x * Wn;     // B*H rows
    float g = g_gray[rowbase + x];
    float t = g_tg[rowbase + x];
    float4 v = make_float4(g, t, g * t, g * g);

    int lane = x & 31, wid = x >> 5;
    #pragma unroll
    for (int o = 1; o < 32; o <<= 1) {
        float ax = __shfl_up_sync(0xffffffffu, v.x, o);
        float ay = __shfl_up_sync(0xffffffffu, v.y, o);
        float az = __shfl_up_sync(0xffffffffu, v.z, o);
        float aw = __shfl_up_sync(0xffffffffu, v.w, o);
        if (lane >= o) { v.x += ax; v.y += ay; v.z += az; v.w += aw; }
    }
    if (lane == 31) wsh[wid] = v;
    __syncthreads();
    if (wid == 0) {
        float4 s = (lane < 16) ? wsh[lane] : make_float4(0.f,0.f,0.f,0.f);
        #pragma unroll
        for (int o = 1; o < 16; o <<= 1) {
            float ax = __shfl_up_sync(0xffffffffu, s.x, o);
            float ay = __shfl_up_sync(0xffffffffu, s.y, o);
            float az = __shfl_up_sync(0xffffffffu, s.z, o);
            float aw = __shfl_up_sync(0xffffffffu, s.w, o);
            if (lane >= o) { s.x += ax; s.y += ay; s.z += az; s.w += aw; }
        }
        if (lane < 16) wsh[lane] = s;
    }
    __syncthreads();
    if (wid > 0) {
        float4 off = wsh[wid - 1];
        v.x += off.x; v.y += off.y; v.z += off.z; v.w += off.w;
    }
    P[x + 1] = v;
    if (x == 0) P[0] = make_float4(0.f,0.f,0.f,0.f);
    __syncthreads();

    int lo = x - r, hi = x + r;
    int a0 = max(0, lo), b0 = min(Wn - 1, hi);
    float4 Pb = P[b0 + 1], Pa = P[a0];
    float4 s = make_float4(Pb.x - Pa.x, Pb.y - Pa.y, Pb.z - Pa.z, Pb.w - Pa.w);
    if (lo < 0) {  // left mirror: indices 1 .. -lo
        float4 q  = P[-lo + 1], q0 = P[1];
        s.x += q.x - q0.x; s.y += q.y - q0.y; s.z += q.z - q0.z; s.w += q.w - q0.w;
    }
    if (hi > Wn - 1) {  // right mirror: indices 2W-2-hi .. W-2
        float4 q  = P[Wn - 1], q0 = P[2 * Wn - 2 - hi];
        s.x += q.x - q0.x; s.y += q.y - q0.y; s.z += q.z - q0.z; s.w += q.w - q0.w;
    }
    g_i4[rowbase + x] = s;
}

// ---------------- K4: vertical box (sliding) + a,b ----------------
__global__ void k_vbox4(const int* __restrict__ rp) {
    int r = clamp_r(rp[0]);
    int k = 2 * r + 1;
    float invk2 = 1.0f / ((float)(k * k));
    int gtid = blockIdx.x * blockDim.x + threadIdx.x;  // 32768 total
    int x = gtid & (Wn - 1);
    int t2 = gtid >> 9;
    int chunk = t2 & 7;
    int b = t2 >> 3;
    if (b >= Bn) return;
    const float4* pl = g_i4 + b * HWn;
    float2* outp = g_ab + b * HWn;
    int y0 = chunk * 64;
    float4 s = make_float4(0.f,0.f,0.f,0.f);
    for (int j = -r; j <= r; j++) {
        int yy = reflecti(y0 + j, Hn);
        float4 q = pl[yy * Wn + x];
        s.x += q.x; s.y += q.y; s.z += q.z; s.w += q.w;
    }
    for (int y = y0; y < y0 + 64; y++) {
        float mI  = s.x * invk2, mp  = s.y * invk2;
        float mIp = s.z * invk2, mII = s.w * invk2;
        float a  = (mIp - mI * mp) / ((mII - mI * mI) + 0.5f);
        float bb = mp - a * mI;
        outp[y * Wn + x] = make_float2(a, bb);
        float4 qi = pl[reflecti(y + r + 1, Hn) * Wn + x];
        float4 qo = pl[reflecti(y - r, Hn) * Wn + x];
        s.x += qi.x - qo.x; s.y += qi.y - qo.y;
        s.z += qi.z - qo.z; s.w += qi.w - qo.w;
    }
}

// ---------------- K5: horizontal box for (a,b) ----------------
__global__ void k_hbox2(const int* __restrict__ rp) {
    int r = clamp_r(rp[0]);
    __shared__ float2 P[Wn + 1];
    __shared__ float2 wsh[16];
    int x = threadIdx.x;
    int rowbase = blockIdx.x * Wn;
    float2 v = g_ab[rowbase + x];

    int lane = x & 31, wid = x >> 5;
    #pragma unroll
    for (int o = 1; o < 32; o <<= 1) {
        float ax = __shfl_up_sync(0xffffffffu, v.x, o);
        float ay = __shfl_up_sync(0xffffffffu, v.y, o);
        if (lane >= o) { v.x += ax; v.y += ay; }
    }
    if (lane == 31) wsh[wid] = v;
    __syncthreads();
    if (wid == 0) {
        float2 s = (lane < 16) ? wsh[lane] : make_float2(0.f,0.f);
        #pragma unroll
        for (int o = 1; o < 16; o <<= 1) {
            float ax = __shfl_up_sync(0xffffffffu, s.x, o);
            float ay = __shfl_up_sync(0xffffffffu, s.y, o);
            if (lane >= o) { s.x += ax; s.y += ay; }
        }
        if (lane < 16) wsh[lane] = s;
    }
    __syncthreads();
    if (wid > 0) { float2 off = wsh[wid - 1]; v.x += off.x; v.y += off.y; }
    P[x + 1] = v;
    if (x == 0) P[0] = make_float2(0.f,0.f);
    __syncthreads();

    int lo = x - r, hi = x + r;
    int a0 = max(0, lo), b0 = min(Wn - 1, hi);
    float2 Pb = P[b0 + 1], Pa = P[a0];
    float2 s = make_float2(Pb.x - Pa.x, Pb.y - Pa.y);
    if (lo < 0)      { float2 q = P[-lo + 1], q0 = P[1];               s.x += q.x - q0.x; s.y += q.y - q0.y; }
    if (hi > Wn - 1) { float2 q = P[Wn - 1],  q0 = P[2*Wn - 2 - hi];   s.x += q.x - q0.x; s.y += q.y - q0.y; }
    g_i2[rowbase + x] = s;
}

// ---------------- K6: vertical box for (a,b) + t_final + J (into d_out) ----------------
__global__ void k_vbox2f(const float* __restrict__ img,
                         const float* __restrict__ A,
                         const int* __restrict__ rp,
                         float* __restrict__ out) {
    int r = clamp_r(rp[0]);
    int k = 2 * r + 1;
    float invk2 = 1.0f / ((float)(k * k));
    int gtid = blockIdx.x * blockDim.x + threadIdx.x;
    int x = gtid & (Wn - 1);
    int t2 = gtid >> 9;
    int chunk = t2 & 7;
    int b = t2 >> 3;
    if (b >= Bn) return;
    const float2* pl = g_i2 + b * HWn;
    int y0 = chunk * 64;
    float2 s = make_float2(0.f, 0.f);
    for (int j = -r; j <= r; j++) {
        int yy = reflecti(y0 + j, Hn);
        float2 q = pl[yy * Wn + x];
        s.x += q.x; s.y += q.y;
    }
    float A0 = A[b*3+0], A1 = A[b*3+1], A2 = A[b*3+2];
    for (int y = y0; y < y0 + 64; y++) {
        float ma = s.x * invk2, mb = s.y * invk2;
        int idx = b * HWn + y * Wn + x;
        float g = g_gray[idx];
        float t = ma * g + mb;
        t = fminf(fmaxf(t, 0.1f), 1.0f);
        float den = t + 1e-8f;
        int p = y * Wn + x;
        float v0 = (img[(b*3+0)*HWn + p] - A0) / den + A0;
        float v1 = (img[(b*3+1)*HWn + p] - A1) / den + A1;
        float v2 = (img[(b*3+2)*HWn + p] - A2) / den + A2;
        out[(b*3+0)*HWn + p] = fminf(fmaxf(v0, 0.f), 1.f);
        out[(b*3+1)*HWn + p] = fminf(fmaxf(v1, 0.f), 1.f);
        out[(b*3+2)*HWn + p] = fminf(fmaxf(v2, 0.f), 1.f);
        float2 qi = pl[reflecti(y + r + 1, Hn) * Wn + x];
        float2 qo = pl[reflecti(y - r, Hn) * Wn + x];
        s.x += qi.x - qo.x; s.y += qi.y - qo.y;
    }
}

// ---------------- histograms & selection (exact radix select on float bits) ----------------
__global__ void k_zero() {
    int i = blockIdx.x * blockDim.x + threadIdx.x;
    if (i < NCH*4096)   g_h1[i] = 0u;
    if (i < NCH*2*256)  g_h2[i] = 0u;
    if (i < NCH*2*1024) g_h3[i] = 0u;
}

__global__ void k_hist1(const float* __restrict__ J) {
    __shared__ unsigned int h[4096];
    for (int i = threadIdx.x; i < 4096; i += 256) h[i] = 0u;
    __syncthreads();
    int ch = blockIdx.y;
    const float* p = J + ch * HWn + blockIdx.x * 8192;
    for (int i = threadIdx.x; i < 8192; i += 256) {
        unsigned int bits = __float_as_uint(p[i]);
        unsigned int bin = bits >> 18;
        if (bin > 4095u) bin = 4095u;
        atomicAdd(&h[bin], 1u);
    }
    __syncthreads();
    for (int i = threadIdx.x; i < 4096; i += 256)
        if (h[i]) atomicAdd(&g_h1[ch*4096 + i], h[i]);
}

__global__ void k_sel1(const float* __restrict__ Ll, const float* __restrict__ Lh) {
    __shared__ unsigned int hsh[4096];
    __shared__ unsigned int seg[256];
    int ch = blockIdx.x;
    unsigned int ssum = 0u;
    for (int j = 0; j < 16; j++) {
        unsigned int vv = g_h1[ch*4096 + threadIdx.x*16 + j];
        hsh[threadIdx.x*16 + j] = vv;
        ssum += vv;
    }
    seg[threadIdx.x] = ssum;
    __syncthreads();
    if (threadIdx.x == 0) {
        int b = ch / 3;
        for (int w = 0; w < 2; w++) {
            float Lv = (w == 0) ? Ll[b] : Lh[b];
            float fr = (Lv / 100.0f) * 262144.0f;
            int rank = (int)fr;
            if (rank < 0) rank = 0;
            if (rank > HWn - 1) rank = HWn - 1;
            unsigned int cum = 0u;
            int sI = 0;
            while (sI < 255 && cum + seg[sI] <= (unsigned int)rank) { cum += seg[sI]; sI++; }
            int bin = sI * 16;
            while (bin < sI*16 + 15 && cum + hsh[bin] <= (unsigned int)rank) { cum += hsh[bin]; bin++; }
            g_t1[ch*2 + w] = bin;
            g_r1[ch*2 + w] = rank - (int)cum;
        }
    }
}

__global__ void k_hist2(const float* __restrict__ J) {
    __shared__ unsigned int h[512];
    for (int i = threadIdx.x; i < 512; i += 256) h[i] = 0u;
    __syncthreads();
    int ch = blockIdx.y;
    int ta = g_t1[ch*2], tb = g_t1[ch*2 + 1];
    const float* p = J + ch * HWn + blockIdx.x * 8192;
    for (int i = threadIdx.x; i < 8192; i += 256) {
        unsigned int bits = __float_as_uint(p[i]);
        int top = (int)(bits >> 18);
        unsigned int mid = (bits >> 10) & 255u;
        if (top == ta) atomicAdd(&h[mid], 1u);
        if (top == tb) atomicAdd(&h[256 + mid], 1u);
    }
    __syncthreads();
    {
        int i = threadIdx.x;
        if (i < 256) {
            if (h[i])       atomicAdd(&g_h2[(ch*2+0)*256 + i], h[i]);
            if (h[256 + i]) atomicAdd(&g_h2[(ch*2+1)*256 + i], h[256 + i]);
        }
    }
}

__global__ void k_sel2() {
    __shared__ unsigned int h[512];
    int ch = blockIdx.x;
    h[threadIdx.x]       = g_h2[(ch*2+0)*256 + threadIdx.x];
    h[256 + threadIdx.x] = g_h2[(ch*2+1)*256 + threadIdx.x];
    __syncthreads();
    if (threadIdx.x == 0) {
        for (int w = 0; w < 2; w++) {
            int rem = g_r1[ch*2 + w];
            unsigned int cum = 0u;
            int bin = 0;
            while (bin < 255 && cum + h[w*256 + bin] <= (unsigned int)rem) { cum += h[w*256 + bin]; bin++; }
            g_t22[ch*2 + w] = (g_t1[ch*2 + w] << 8) | bin;
            g_r2[ch*2 + w]  = rem - (int)cum;
        }
    }
}

__global__ void k_hist3(const float* __restrict__ J) {
    __shared__ unsigned int h[2048];
    for (int i = threadIdx.x; i < 2048; i += 256) h[i] = 0u;
    __syncthreads();
    int ch = blockIdx.y;
    int ta = g_t22[ch*2], tb = g_t22[ch*2 + 1];
    const float* p = J + ch * HWn + blockIdx.x * 8192;
    for (int i = threadIdx.x; i < 8192; i += 256) {
        unsigned int bits = __float_as_uint(p[i]);
        int top = (int)(bits >> 10);
        unsigned int lo = bits & 1023u;
        if (top == ta) atomicAdd(&h[lo], 1u);
        if (top == tb) atomicAdd(&h[1024 + lo], 1u);
    }
    __syncthreads();
    for (int i = threadIdx.x; i < 2048; i += 256)
        if (h[i]) atomicAdd(&g_h3[ch*2048 + i], h[i]);
}

__global__ void k_sel3() {
    __shared__ unsigned int h[2048];
    int ch = blockIdx.x;
    for (int i = threadIdx.x; i < 2048; i += 256) h[i] = g_h3[ch*2048 + i];
    __syncthreads();
    if (threadIdx.x == 0) {
        for (int w = 0; w < 2; w++) {
            int rem = g_r2[ch*2 + w];
            unsigned int cum = 0u;
            int bin = 0;
            while (bin < 1023 && cum + h[w*1024 + bin] <= (unsigned int)rem) { cum += h[w*1024 + bin]; bin++; }
            unsigned int bits = ((unsigned int)g_t22[ch*2 + w] << 10) | (unsigned int)bin;
            float pv = __uint_as_float(bits);
            if (w == 0) g_pl[ch] = pv; else g_ph[ch] = pv;
        }
    }
}

// ---------------- final normalize (in place on d_out) ----------------
__global__ void k_final(float* __restrict__ out) {
    int i = blockIdx.x * blockDim.x + threadIdx.x;
    if (i >= 3 * BHWn) return;
    int ch = i >> 18;
    float pl = g_pl[ch], ph = g_ph[ch];
    float v = out[i];
    v = fminf(fmaxf(v, pl), ph);
    v = (v - pl) / (ph - pl + 1e-8f);
    out[i] = fminf(fmaxf(v, 0.f), 1.f);
}

// ---------------- launch ----------------
extern "C" void kernel_launch(void* const* d_in, const int* in_sizes, int n_in,
                              void* d_out, int out_size) {
    const float* img   = (const float*)d_in[0];
    const float* omega = (const float*)d_in[1];
    const float* A     = (const float*)d_in[2];
    const float* Ll    = (const float*)d_in[3];
    const float* Lh    = (const float*)d_in[4];
    const int*   rp    = (const int*)d_in[5];
    float* out = (float*)d_out;

    k_pre  <<<BHWn/256, 256>>>(img, omega, A);
    k_tg   <<<BHWn/256, 256>>>();
    k_hbox4<<<Bn*Hn, 512>>>(rp);
    k_vbox4<<<(Bn*Wn*(Hn/64))/256, 256>>>(rp);
    k_hbox2<<<Bn*Hn, 512>>>(rp);
    k_vbox2f<<<(Bn*Wn*(Hn/64))/256, 256>>>(img, A, rp, out);
    k_zero <<<(NCH*4096 + 255)/256, 256>>>();
    k_hist1<<<dim3(32, NCH), 256>>>(out);
    k_sel1 <<<NCH, 256>>>(Ll, Lh);
    k_hist2<<<dim3(32, NCH), 256>>>(out);
    k_sel2 <<<NCH, 256>>>();
    k_hist3<<<dim3(32, NCH), 256>>>(out);
    k_sel3 <<<NCH, 256>>>();
    k_final<<<(3*BHWn)/256, 256>>>(out);
}

// round 2
// speedup vs baseline: 1.7161x; 1.7161x over previous
#include <cuda_runtime.h>
#include <math.h>

#define Bn   8
#define Hn   512
#define Wn   512
#define HWn  (Hn*Wn)      // 262144 = 2^18
#define BHWn (Bn*HWn)     // 2097152
#define NCH  24           // B*3 channels for percentile
#define CH   32           // rows per thread in vertical kernels

// ---------------- scratch (static device globals; no allocation) ----------------
__device__ float4 g_i4[BHWn];    // H-pass sums of (gray, tg, gray*tg, gray*gray)
__device__ float2 g_ab[BHWn];    // (a, b) guided filter coefficients
__device__ float2 g_i2[BHWn];    // H-pass sums of (a, b)
__device__ unsigned int g_h1[NCH*4096];
__device__ unsigned int g_h2[NCH*2*256];
__device__ unsigned int g_h3[NCH*2*1024];
__device__ int   g_t1[NCH*2];
__device__ int   g_r1[NCH*2];
__device__ int   g_t22[NCH*2];
__device__ int   g_r2[NCH*2];
__device__ float g_pl[NCH];
__device__ float g_ph[NCH];

__device__ __forceinline__ int reflecti(int i, int n) {
    if (i < 0) i = -i;
    if (i > n - 1) i = 2 * (n - 1) - i;
    return i;
}
__device__ __forceinline__ int clamp_r(int r) {
    if (r < 1) r = 1;
    if (r > 50) r = 50;
    return r;
}

// ---------------- K1: fused t0/gray/tg + horizontal box (4 planes) ----------------
__global__ void k_hbox4(const float* __restrict__ img,
                        const float* __restrict__ omega,
                        const float* __restrict__ Aa,
                        const int* __restrict__ rp) {
    int r = clamp_r(rp[0]);
    __shared__ float4 P[Wn + 1];
    __shared__ float4 wsh[16];
    __shared__ float t0s[Wn];
    int x = threadIdx.x;               // 512 threads
    int rowid = blockIdx.x;            // B*H rows
    int b = rowid >> 9, y = rowid & 511;
    int ys = (y == 0) ? 0 : y - 1;

    // zero g_h1 for the later hist pass (4096 blocks * 24 = 98304 entries)
    if (x < NCH) g_h1[rowid * NCH + x] = 0u;

    const float* ib = img + b * 3 * HWn;
    float a0 = Aa[b*3+0] + 1e-8f;
    float a1 = Aa[b*3+1] + 1e-8f;
    float a2 = Aa[b*3+2] + 1e-8f;
    float om = omega[b];

    float rv = ib[y*Wn + x];
    float gv = ib[HWn + y*Wn + x];
    float bv = ib[2*HWn + y*Wn + x];
    float t0y = 1.0f - om * fminf(fminf(rv/a0, gv/a1), bv/a2);
    float t0yv;
    if (ys == y) {
        t0yv = t0y;
    } else {
        float rs = ib[ys*Wn + x];
        float gs = ib[HWn + ys*Wn + x];
        float bs = ib[2*HWn + ys*Wn + x];
        t0yv = 1.0f - om * fminf(fminf(rs/a0, gs/a1), bs/a2);
    }
    t0s[x] = t0yv;
    float gray = 0.299f * rv + 0.587f * gv + 0.114f * bv;
    __syncthreads();

    float txv;
    if (x == 0) {
        txv = t0s[0];
    } else {
        float tp = t0s[x - 1];
        txv = tp * __expf(-fabsf(t0yv - tp));
    }
    // when y==0, ys==y so the factor is exp(0)=1 (matches tg definition)
    float tgv = txv * __expf(-fabsf(t0y - t0yv));

    float4 v = make_float4(gray, tgv, gray * tgv, gray * gray);

    int lane = x & 31, wid = x >> 5;
    #pragma unroll
    for (int o = 1; o < 32; o <<= 1) {
        float ax = __shfl_up_sync(0xffffffffu, v.x, o);
        float ay = __shfl_up_sync(0xffffffffu, v.y, o);
        float az = __shfl_up_sync(0xffffffffu, v.z, o);
        float aw = __shfl_up_sync(0xffffffffu, v.w, o);
        if (lane >= o) { v.x += ax; v.y += ay; v.z += az; v.w += aw; }
    }
    if (lane == 31) wsh[wid] = v;
    __syncthreads();
    if (wid == 0) {
        float4 s = (lane < 16) ? wsh[lane] : make_float4(0.f,0.f,0.f,0.f);
        #pragma unroll
        for (int o = 1; o < 16; o <<= 1) {
            float ax = __shfl_up_sync(0xffffffffu, s.x, o);
            float ay = __shfl_up_sync(0xffffffffu, s.y, o);
            float az = __shfl_up_sync(0xffffffffu, s.z, o);
            float aw = __shfl_up_sync(0xffffffffu, s.w, o);
            if (lane >= o) { s.x += ax; s.y += ay; s.z += az; s.w += aw; }
        }
        if (lane < 16) wsh[lane] = s;
    }
    __syncthreads();
    if (wid > 0) {
        float4 off = wsh[wid - 1];
        v.x += off.x; v.y += off.y; v.z += off.z; v.w += off.w;
    }
    P[x + 1] = v;
    if (x == 0) P[0] = make_float4(0.f,0.f,0.f,0.f);
    __syncthreads();

    int lo = x - r, hi = x + r;
    int ai = max(0, lo), bi = min(Wn - 1, hi);
    float4 Pb = P[bi + 1], Pa = P[ai];
    float4 s = make_float4(Pb.x - Pa.x, Pb.y - Pa.y, Pb.z - Pa.z, Pb.w - Pa.w);
    if (lo < 0) {
        float4 q  = P[-lo + 1], q0 = P[1];
        s.x += q.x - q0.x; s.y += q.y - q0.y; s.z += q.z - q0.z; s.w += q.w - q0.w;
    }
    if (hi > Wn - 1) {
        float4 q  = P[Wn - 1], q0 = P[2 * Wn - 2 - hi];
        s.x += q.x - q0.x; s.y += q.y - q0.y; s.z += q.z - q0.z; s.w += q.w - q0.w;
    }
    g_i4[rowid * Wn + x] = s;
}

// ---------------- K2: vertical box (sliding) + a,b ----------------
__global__ void k_vbox4(const int* __restrict__ rp) {
    int r = clamp_r(rp[0]);
    int k = 2 * r + 1;
    float invk2 = 1.0f / ((float)(k * k));
    int gtid = blockIdx.x * blockDim.x + threadIdx.x;  // 65536 total
    int x = gtid & (Wn - 1);
    int t2 = gtid >> 9;
    int chunk = t2 & (Hn/CH - 1);
    int b = t2 >> 4;
    const float4* __restrict__ base = g_i4 + b * HWn + x;
    float2* __restrict__ outp = g_ab + b * HWn + x;
    int y0 = chunk * CH;
    float4 s = make_float4(0.f,0.f,0.f,0.f);
    if (y0 - r >= 0 && y0 + r + CH <= Hn - 1) {
        #pragma unroll 4
        for (int j = -r; j <= r; j++) {
            float4 q = base[(y0 + j) * Wn];
            s.x += q.x; s.y += q.y; s.z += q.z; s.w += q.w;
        }
        #pragma unroll 4
        for (int y = y0; y < y0 + CH; y++) {
            float mI  = s.x * invk2, mp  = s.y * invk2;
            float mIp = s.z * invk2, mII = s.w * invk2;
            float a  = (mIp - mI * mp) / ((mII - mI * mI) + 0.5f);
            outp[y * Wn] = make_float2(a, mp - a * mI);
            float4 qi = base[(y + r + 1) * Wn];
            float4 qo = base[(y - r) * Wn];
            s.x += qi.x - qo.x; s.y += qi.y - qo.y;
            s.z += qi.z - qo.z; s.w += qi.w - qo.w;
        }
    } else {
        #pragma unroll 4
        for (int j = -r; j <= r; j++) {
            float4 q = base[reflecti(y0 + j, Hn) * Wn];
            s.x += q.x; s.y += q.y; s.z += q.z; s.w += q.w;
        }
        #pragma unroll 2
        for (int y = y0; y < y0 + CH; y++) {
            float mI  = s.x * invk2, mp  = s.y * invk2;
            float mIp = s.z * invk2, mII = s.w * invk2;
            float a  = (mIp - mI * mp) / ((mII - mI * mI) + 0.5f);
            outp[y * Wn] = make_float2(a, mp - a * mI);
            float4 qi = base[reflecti(y + r + 1, Hn) * Wn];
            float4 qo = base[reflecti(y - r, Hn) * Wn];
            s.x += qi.x - qo.x; s.y += qi.y - qo.y;
            s.z += qi.z - qo.z; s.w += qi.w - qo.w;
        }
    }
}

// ---------------- K3: horizontal box for (a,b) ----------------
__global__ void k_hbox2(const int* __restrict__ rp) {
    int r = clamp_r(rp[0]);
    __shared__ float2 P[Wn + 1];
    __shared__ float2 wsh[16];
    int x = threadIdx.x;
    int rowbase = blockIdx.x * Wn;
    float2 v = g_ab[rowbase + x];

    int lane = x & 31, wid = x >> 5;
    #pragma unroll
    for (int o = 1; o < 32; o <<= 1) {
        float ax = __shfl_up_sync(0xffffffffu, v.x, o);
        float ay = __shfl_up_sync(0xffffffffu, v.y, o);
        if (lane >= o) { v.x += ax; v.y += ay; }
    }
    if (lane == 31) wsh[wid] = v;
    __syncthreads();
    if (wid == 0) {
        float2 s = (lane < 16) ? wsh[lane] : make_float2(0.f,0.f);
        #pragma unroll
        for (int o = 1; o < 16; o <<= 1) {
            float ax = __shfl_up_sync(0xffffffffu, s.x, o);
            float ay = __shfl_up_sync(0xffffffffu, s.y, o);
            if (lane >= o) { s.x += ax; s.y += ay; }
        }
        if (lane < 16) wsh[lane] = s;
    }
    __syncthreads();
    if (wid > 0) { float2 off = wsh[wid - 1]; v.x += off.x; v.y += off.y; }
    P[x + 1] = v;
    if (x == 0) P[0] = make_float2(0.f,0.f);
    __syncthreads();

    int lo = x - r, hi = x + r;
    int ai = max(0, lo), bi = min(Wn - 1, hi);
    float2 Pb = P[bi + 1], Pa = P[ai];
    float2 s = make_float2(Pb.x - Pa.x, Pb.y - Pa.y);
    if (lo < 0)      { float2 q = P[-lo + 1], q0 = P[1];               s.x += q.x - q0.x; s.y += q.y - q0.y; }
    if (hi > Wn - 1) { float2 q = P[Wn - 1],  q0 = P[2*Wn - 2 - hi];   s.x += q.x - q0.x; s.y += q.y - q0.y; }
    g_i2[rowbase + x] = s;
}

// ---------------- K4: vertical box for (a,b) + t_final + J (into d_out) ----------------
__global__ void k_vbox2f(const float* __restrict__ img,
                         const float* __restrict__ Aa,
                         const int* __restrict__ rp,
                         float* __restrict__ out) {
    int r = clamp_r(rp[0]);
    int k = 2 * r + 1;
    float invk2 = 1.0f / ((float)(k * k));
    int gtid = blockIdx.x * blockDim.x + threadIdx.x;
    int x = gtid & (Wn - 1);
    int t2 = gtid >> 9;
    int chunk = t2 & (Hn/CH - 1);
    int b = t2 >> 4;
    const float2* __restrict__ base = g_i2 + b * HWn + x;
    const float* __restrict__ i0 = img + b * 3 * HWn + x;
    float* __restrict__ o0 = out + b * 3 * HWn + x;
    int y0 = chunk * CH;
    float A0 = Aa[b*3+0], A1 = Aa[b*3+1], A2 = Aa[b*3+2];
    float2 s = make_float2(0.f, 0.f);
    bool interior = (y0 - r >= 0) && (y0 + r + CH <= Hn - 1);
    if (interior) {
        #pragma unroll 4
        for (int j = -r; j <= r; j++) {
            float2 q = base[(y0 + j) * Wn];
            s.x += q.x; s.y += q.y;
        }
    } else {
        #pragma unroll 4
        for (int j = -r; j <= r; j++) {
            float2 q = base[reflecti(y0 + j, Hn) * Wn];
            s.x += q.x; s.y += q.y;
        }
    }
    #pragma unroll 2
    for (int y = y0; y < y0 + CH; y++) {
        float ma = s.x * invk2, mb = s.y * invk2;
        float rv = i0[y*Wn], gv = i0[HWn + y*Wn], bv = i0[2*HWn + y*Wn];
        float gray = 0.299f * rv + 0.587f * gv + 0.114f * bv;
        float t = fminf(fmaxf(ma * gray + mb, 0.1f), 1.0f);
        float inv = 1.0f / (t + 1e-8f);
        o0[y*Wn]         = fminf(fmaxf((rv - A0) * inv + A0, 0.f), 1.f);
        o0[HWn + y*Wn]   = fminf(fmaxf((gv - A1) * inv + A1, 0.f), 1.f);
        o0[2*HWn + y*Wn] = fminf(fmaxf((bv - A2) * inv + A2, 0.f), 1.f);
        float2 qi, qo;
        if (interior) {
            qi = base[(y + r + 1) * Wn];
            qo = base[(y - r) * Wn];
        } else {
            qi = base[reflecti(y + r + 1, Hn) * Wn];
            qo = base[reflecti(y - r, Hn) * Wn];
        }
        s.x += qi.x - qo.x; s.y += qi.y - qo.y;
    }
}

// ---------------- histograms & selection (exact radix select on float bits) ----------------
__global__ void k_hist1(const float* __restrict__ J) {
    __shared__ unsigned int h[4096];
    for (int i = threadIdx.x; i < 4096; i += 256) h[i] = 0u;
    __syncthreads();
    int ch = blockIdx.y;
    const float4* p = (const float4*)(J + ch * HWn + blockIdx.x * 8192);
    for (int i = threadIdx.x; i < 2048; i += 256) {
        float4 v = p[i];
        unsigned int b0 = __float_as_uint(v.x) >> 18;
        unsigned int b1 = __float_as_uint(v.y) >> 18;
        unsigned int b2 = __float_as_uint(v.z) >> 18;
        unsigned int b3 = __float_as_uint(v.w) >> 18;
        atomicAdd(&h[min(b0, 4095u)], 1u);
        atomicAdd(&h[min(b1, 4095u)], 1u);
        atomicAdd(&h[min(b2, 4095u)], 1u);
        atomicAdd(&h[min(b3, 4095u)], 1u);
    }
    __syncthreads();
    for (int i = threadIdx.x; i < 4096; i += 256)
        if (h[i]) atomicAdd(&g_h1[ch*4096 + i], h[i]);
}

__global__ void k_sel1(const float* __restrict__ Ll, const float* __restrict__ Lh) {
    __shared__ unsigned int hsh[4096];
    __shared__ unsigned int seg[256];
    int ch = blockIdx.x;
    // zero g_h2 for the next pass
    g_h2[ch*512 + threadIdx.x] = 0u;
    g_h2[ch*512 + 256 + threadIdx.x] = 0u;
    unsigned int ssum = 0u;
    for (int j = 0; j < 16; j++) {
        unsigned int vv = g_h1[ch*4096 + threadIdx.x*16 + j];
        hsh[threadIdx.x*16 + j] = vv;
        ssum += vv;
    }
    seg[threadIdx.x] = ssum;
    __syncthreads();
    if (threadIdx.x == 0) {
        int b = ch / 3;
        for (int w = 0; w < 2; w++) {
            float Lv = (w == 0) ? Ll[b] : Lh[b];
            float fr = (Lv / 100.0f) * 262144.0f;
            int rank = (int)fr;
            if (rank < 0) rank = 0;
            if (rank > HWn - 1) rank = HWn - 1;
            unsigned int cum = 0u;
            int sI = 0;
            while (sI < 255 && cum + seg[sI] <= (unsigned int)rank) { cum += seg[sI]; sI++; }
            int bin = sI * 16;
            while (bin < sI*16 + 15 && cum + hsh[bin] <= (unsigned int)rank) { cum += hsh[bin]; bin++; }
            g_t1[ch*2 + w] = bin;
            g_r1[ch*2 + w] = rank - (int)cum;
        }
    }
}

__global__ void k_hist2(const float* __restrict__ J) {
    __shared__ unsigned int h[512];
    for (int i = threadIdx.x; i < 512; i += 256) h[i] = 0u;
    __syncthreads();
    int ch = blockIdx.y;
    int ta = g_t1[ch*2], tb = g_t1[ch*2 + 1];
    const float4* p = (const float4*)(J + ch * HWn + blockIdx.x * 8192);
    for (int i = threadIdx.x; i < 2048; i += 256) {
        float4 v = p[i];
        unsigned int bb[4] = {__float_as_uint(v.x), __float_as_uint(v.y),
                              __float_as_uint(v.z), __float_as_uint(v.w)};
        #pragma unroll
        for (int j = 0; j < 4; j++) {
            int top = (int)(bb[j] >> 18);
            unsigned int mid = (bb[j] >> 10) & 255u;
            if (top == ta) atomicAdd(&h[mid], 1u);
            if (top == tb) atomicAdd(&h[256 + mid], 1u);
        }
    }
    __syncthreads();
    {
        int i = threadIdx.x;
        if (h[i])       atomicAdd(&g_h2[(ch*2+0)*256 + i], h[i]);
        if (h[256 + i]) atomicAdd(&g_h2[(ch*2+1)*256 + i], h[256 + i]);
    }
}

__global__ void k_sel2() {
    __shared__ unsigned int h[512];
    int ch = blockIdx.x;
    // zero g_h3 for the next pass
    for (int i = 0; i < 8; i++)
        g_h3[ch*2048 + i*256 + threadIdx.x] = 0u;
    h[threadIdx.x]       = g_h2[(ch*2+0)*256 + threadIdx.x];
    h[256 + threadIdx.x] = g_h2[(ch*2+1)*256 + threadIdx.x];
    __syncthreads();
    if (threadIdx.x == 0) {
        for (int w = 0; w < 2; w++) {
            int rem = g_r1[ch*2 + w];
            unsigned int cum = 0u;
            int bin = 0;
            while (bin < 255 && cum + h[w*256 + bin] <= (unsigned int)rem) { cum += h[w*256 + bin]; bin++; }
            g_t22[ch*2 + w] = (g_t1[ch*2 + w] << 8) | bin;
            g_r2[ch*2 + w]  = rem - (int)cum;
        }
    }
}

__global__ void k_hist3(const float* __restrict__ J) {
    __shared__ unsigned int h[2048];
    for (int i = threadIdx.x; i < 2048; i += 256) h[i] = 0u;
    __syncthreads();
    int ch = blockIdx.y;
    int ta = g_t22[ch*2], tb = g_t22[ch*2 + 1];
    const float4* p = (const float4*)(J + ch * HWn + blockIdx.x * 8192);
    for (int i = threadIdx.x; i < 2048; i += 256) {
        float4 v = p[i];
        unsigned int bb[4] = {__float_as_uint(v.x), __float_as_uint(v.y),
                              __float_as_uint(v.z), __float_as_uint(v.w)};
        #pragma unroll
        for (int j = 0; j < 4; j++) {
            int top = (int)(bb[j] >> 10);
            unsigned int lo = bb[j] & 1023u;
            if (top == ta) atomicAdd(&h[lo], 1u);
            if (top == tb) atomicAdd(&h[1024 + lo], 1u);
        }
    }
    __syncthreads();
    for (int i = threadIdx.x; i < 2048; i += 256)
        if (h[i]) atomicAdd(&g_h3[ch*2048 + i], h[i]);
}

__global__ void k_sel3() {
    __shared__ unsigned int h[2048];
    int ch = blockIdx.x;
    for (int i = threadIdx.x; i < 2048; i += 256) h[i] = g_h3[ch*2048 + i];
    __syncthreads();
    if (threadIdx.x == 0) {
        for (int w = 0; w < 2; w++) {
            int rem = g_r2[ch*2 + w];
            unsigned int cum = 0u;
            int bin = 0;
            while (bin < 1023 && cum + h[w*1024 + bin] <= (unsigned int)rem) { cum += h[w*1024 + bin]; bin++; }
            unsigned int bits = ((unsigned int)g_t22[ch*2 + w] << 10) | (unsigned int)bin;
            float pv = __uint_as_float(bits);
            if (w == 0) g_pl[ch] = pv; else g_ph[ch] = pv;
        }
    }
}

// ---------------- final normalize (in place on d_out), float4 ----------------
__global__ void k_final(float* __restrict__ out) {
    int i = blockIdx.x * blockDim.x + threadIdx.x;   // float4 index
    if (i >= 3 * BHWn / 4) return;
    int ch = i >> 16;            // (i*4) >> 18
    float pl = g_pl[ch], ph = g_ph[ch];
    float inv = 1.0f / (ph - pl + 1e-8f);
    float4 v = ((float4*)out)[i];
    v.x = fminf(fmaxf((fminf(fmaxf(v.x, pl), ph) - pl) * inv, 0.f), 1.f);
    v.y = fminf(fmaxf((fminf(fmaxf(v.y, pl), ph) - pl) * inv, 0.f), 1.f);
    v.z = fminf(fmaxf((fminf(fmaxf(v.z, pl), ph) - pl) * inv, 0.f), 1.f);
    v.w = fminf(fmaxf((fminf(fmaxf(v.w, pl), ph) - pl) * inv, 0.f), 1.f);
    ((float4*)out)[i] = v;
}

// ---------------- launch ----------------
extern "C" void kernel_launch(void* const* d_in, const int* in_sizes, int n_in,
                              void* d_out, int out_size) {
    const float* img   = (const float*)d_in[0];
    const float* omega = (const float*)d_in[1];
    const float* A     = (const float*)d_in[2];
    const float* Ll    = (const float*)d_in[3];
    const float* Lh    = (const float*)d_in[4];
    const int*   rp    = (const int*)d_in[5];
    float* out = (float*)d_out;

    k_hbox4 <<<Bn*Hn, 512>>>(img, omega, A, rp);
    k_vbox4 <<<(Bn*Wn*(Hn/CH))/256, 256>>>(rp);
    k_hbox2 <<<Bn*Hn, 512>>>(rp);
    k_vbox2f<<<(Bn*Wn*(Hn/CH))/256, 256>>>(img, A, rp, out);
    k_hist1 <<<dim3(32, NCH), 256>>>(out);
    k_sel1  <<<NCH, 256>>>(Ll, Lh);
    k_hist2 <<<dim3(32, NCH), 256>>>(out);
    k_sel2  <<<NCH, 256>>>();
    k_hist3 <<<dim3(32, NCH), 256>>>(out);
    k_sel3  <<<NCH, 256>>>();
    k_final <<<(3*BHWn/4 + 255)/256, 256>>>(out);
}

// round 3
// speedup vs baseline: 1.8668x; 1.0878x over previous
#include <cuda_runtime.h>
#include <math.h>

#define Bn   8
#define Hn   512
#define Wn   512
#define HWn  (Hn*Wn)      // 262144 = 2^18
#define BHWn (Bn*HWn)     // 2097152
#define NCH  24           // B*3 channels for percentile
#define CH   16           // rows per thread in vertical kernels

// ---------------- scratch (static device globals; no allocation) ----------------
__device__ float4 g_i4[BHWn];    // H-pass sums of (gray, tg, gray*tg, gray*gray)
__device__ float2 g_ab[BHWn];    // (a, b) guided filter coefficients
__device__ float2 g_i2[BHWn];    // H-pass sums of (a, b)
__device__ unsigned int g_h1[NCH*4096];
__device__ unsigned int g_h2[NCH*2*256];
__device__ unsigned int g_h3[NCH*2*1024];
__device__ int   g_t1[NCH*2];
__device__ int   g_r1[NCH*2];
__device__ int   g_t22[NCH*2];
__device__ int   g_r2[NCH*2];
__device__ float g_pl[NCH];
__device__ float g_ph[NCH];

__device__ __forceinline__ int reflecti(int i, int n) {
    if (i < 0) i = -i;
    if (i > n - 1) i = 2 * (n - 1) - i;
    return i;
}
__device__ __forceinline__ int clamp_r(int r) {
    if (r < 1) r = 1;
    if (r > 50) r = 50;
    return r;
}

// ---------------- K1: fused t0/gray/tg + horizontal box (4 planes) ----------------
__global__ void k_hbox4(const float* __restrict__ img,
                        const float* __restrict__ omega,
                        const float* __restrict__ Aa,
                        const int* __restrict__ rp) {
    int r = clamp_r(rp[0]);
    __shared__ float4 P[Wn + 1];
    __shared__ float4 wsh[16];
    __shared__ float t0s[Wn];
    int x = threadIdx.x;               // 512 threads
    int rowid = blockIdx.x;            // B*H rows
    int b = rowid >> 9, y = rowid & 511;
    int ys = (y == 0) ? 0 : y - 1;

    // zero g_h1 for the later hist pass (4096 blocks * 24 = 98304 entries)
    if (x < NCH) g_h1[rowid * NCH + x] = 0u;

    const float* ib = img + b * 3 * HWn;
    float a0 = Aa[b*3+0] + 1e-8f;
    float a1 = Aa[b*3+1] + 1e-8f;
    float a2 = Aa[b*3+2] + 1e-8f;
    float om = omega[b];

    float rv = ib[y*Wn + x];
    float gv = ib[HWn + y*Wn + x];
    float bv = ib[2*HWn + y*Wn + x];
    float t0y = 1.0f - om * fminf(fminf(rv/a0, gv/a1), bv/a2);
    float t0yv;
    if (ys == y) {
        t0yv = t0y;
    } else {
        float rs = ib[ys*Wn + x];
        float gs = ib[HWn + ys*Wn + x];
        float bs = ib[2*HWn + ys*Wn + x];
        t0yv = 1.0f - om * fminf(fminf(rs/a0, gs/a1), bs/a2);
    }
    t0s[x] = t0yv;
    float gray = 0.299f * rv + 0.587f * gv + 0.114f * bv;
    __syncthreads();

    float txv;
    if (x == 0) {
        txv = t0s[0];
    } else {
        float tp = t0s[x - 1];
        txv = tp * __expf(-fabsf(t0yv - tp));
    }
    float tgv = txv * __expf(-fabsf(t0y - t0yv));

    float4 v = make_float4(gray, tgv, gray * tgv, gray * gray);

    int lane = x & 31, wid = x >> 5;
    #pragma unroll
    for (int o = 1; o < 32; o <<= 1) {
        float ax = __shfl_up_sync(0xffffffffu, v.x, o);
        float ay = __shfl_up_sync(0xffffffffu, v.y, o);
        float az = __shfl_up_sync(0xffffffffu, v.z, o);
        float aw = __shfl_up_sync(0xffffffffu, v.w, o);
        if (lane >= o) { v.x += ax; v.y += ay; v.z += az; v.w += aw; }
    }
    if (lane == 31) wsh[wid] = v;
    __syncthreads();
    if (wid == 0) {
        float4 s = (lane < 16) ? wsh[lane] : make_float4(0.f,0.f,0.f,0.f);
        #pragma unroll
        for (int o = 1; o < 16; o <<= 1) {
            float ax = __shfl_up_sync(0xffffffffu, s.x, o);
            float ay = __shfl_up_sync(0xffffffffu, s.y, o);
            float az = __shfl_up_sync(0xffffffffu, s.z, o);
            float aw = __shfl_up_sync(0xffffffffu, s.w, o);
            if (lane >= o) { s.x += ax; s.y += ay; s.z += az; s.w += aw; }
        }
        if (lane < 16) wsh[lane] = s;
    }
    __syncthreads();
    if (wid > 0) {
        float4 off = wsh[wid - 1];
        v.x += off.x; v.y += off.y; v.z += off.z; v.w += off.w;
    }
    P[x + 1] = v;
    if (x == 0) P[0] = make_float4(0.f,0.f,0.f,0.f);
    __syncthreads();

    int lo = x - r, hi = x + r;
    int ai = max(0, lo), bi = min(Wn - 1, hi);
    float4 Pb = P[bi + 1], Pa = P[ai];
    float4 s = make_float4(Pb.x - Pa.x, Pb.y - Pa.y, Pb.z - Pa.z, Pb.w - Pa.w);
    if (lo < 0) {
        float4 q  = P[-lo + 1], q0 = P[1];
        s.x += q.x - q0.x; s.y += q.y - q0.y; s.z += q.z - q0.z; s.w += q.w - q0.w;
    }
    if (hi > Wn - 1) {
        float4 q  = P[Wn - 1], q0 = P[2 * Wn - 2 - hi];
        s.x += q.x - q0.x; s.y += q.y - q0.y; s.z += q.z - q0.z; s.w += q.w - q0.w;
    }
    g_i4[rowid * Wn + x] = s;
}

// ---------------- K2: vertical box (sliding), 2 columns/thread + a,b ----------------
__global__ void k_vbox4(const int* __restrict__ rp) {
    int r = clamp_r(rp[0]);
    int k = 2 * r + 1;
    float invk2 = 1.0f / ((float)(k * k));
    int gtid = blockIdx.x * blockDim.x + threadIdx.x;  // 65536 total
    int px = gtid & 255;                // column pair 0..255
    int t2 = gtid >> 8;
    int chunk = t2 & (Hn/CH - 1);
    int b = t2 >> 5;
    const float4* __restrict__ base = g_i4 + b * HWn + px * 2;
    float4* __restrict__ gab4 = (float4*)g_ab + (b * HWn >> 1) + px;
    int y0 = chunk * CH;
    float4 s0 = make_float4(0.f,0.f,0.f,0.f);
    float4 s1 = make_float4(0.f,0.f,0.f,0.f);
    if (y0 - r >= 0 && y0 + r + CH <= Hn - 1) {
        #pragma unroll 4
        for (int j = -r; j <= r; j++) {
            float4 q0 = base[(y0 + j) * Wn];
            float4 q1 = base[(y0 + j) * Wn + 1];
            s0.x += q0.x; s0.y += q0.y; s0.z += q0.z; s0.w += q0.w;
            s1.x += q1.x; s1.y += q1.y; s1.z += q1.z; s1.w += q1.w;
        }
        #pragma unroll 4
        for (int y = y0; y < y0 + CH; y++) {
            float mI0  = s0.x * invk2, mp0  = s0.y * invk2;
            float mIp0 = s0.z * invk2, mII0 = s0.w * invk2;
            float a0 = (mIp0 - mI0 * mp0) / ((mII0 - mI0 * mI0) + 0.5f);
            float mI1  = s1.x * invk2, mp1  = s1.y * invk2;
            float mIp1 = s1.z * invk2, mII1 = s1.w * invk2;
            float a1 = (mIp1 - mI1 * mp1) / ((mII1 - mI1 * mI1) + 0.5f);
            gab4[y * (Wn/2)] = make_float4(a0, mp0 - a0 * mI0, a1, mp1 - a1 * mI1);
            float4 qi0 = base[(y + r + 1) * Wn];
            float4 qi1 = base[(y + r + 1) * Wn + 1];
            float4 qo0 = base[(y - r) * Wn];
            float4 qo1 = base[(y - r) * Wn + 1];
            s0.x += qi0.x - qo0.x; s0.y += qi0.y - qo0.y;
            s0.z += qi0.z - qo0.z; s0.w += qi0.w - qo0.w;
            s1.x += qi1.x - qo1.x; s1.y += qi1.y - qo1.y;
            s1.z += qi1.z - qo1.z; s1.w += qi1.w - qo1.w;
        }
    } else {
        #pragma unroll 4
        for (int j = -r; j <= r; j++) {
            int yy = reflecti(y0 + j, Hn);
            float4 q0 = base[yy * Wn];
            float4 q1 = base[yy * Wn + 1];
            s0.x += q0.x; s0.y += q0.y; s0.z += q0.z; s0.w += q0.w;
            s1.x += q1.x; s1.y += q1.y; s1.z += q1.z; s1.w += q1.w;
        }
        #pragma unroll 2
        for (int y = y0; y < y0 + CH; y++) {
            float mI0  = s0.x * invk2, mp0  = s0.y * invk2;
            float mIp0 = s0.z * invk2, mII0 = s0.w * invk2;
            float a0 = (mIp0 - mI0 * mp0) / ((mII0 - mI0 * mI0) + 0.5f);
            float mI1  = s1.x * invk2, mp1  = s1.y * invk2;
            float mIp1 = s1.z * invk2, mII1 = s1.w * invk2;
            float a1 = (mIp1 - mI1 * mp1) / ((mII1 - mI1 * mI1) + 0.5f);
            gab4[y * (Wn/2)] = make_float4(a0, mp0 - a0 * mI0, a1, mp1 - a1 * mI1);
            int yi = reflecti(y + r + 1, Hn), yo = reflecti(y - r, Hn);
            float4 qi0 = base[yi * Wn];
            float4 qi1 = base[yi * Wn + 1];
            float4 qo0 = base[yo * Wn];
            float4 qo1 = base[yo * Wn + 1];
            s0.x += qi0.x - qo0.x; s0.y += qi0.y - qo0.y;
            s0.z += qi0.z - qo0.z; s0.w += qi0.w - qo0.w;
            s1.x += qi1.x - qo1.x; s1.y += qi1.y - qo1.y;
            s1.z += qi1.z - qo1.z; s1.w += qi1.w - qo1.w;
        }
    }
}

// ---------------- K3: horizontal box for (a,b) ----------------
__global__ void k_hbox2(const int* __restrict__ rp) {
    int r = clamp_r(rp[0]);
    __shared__ float2 P[Wn + 1];
    __shared__ float2 wsh[16];
    int x = threadIdx.x;
    int rowbase = blockIdx.x * Wn;
    float2 v = g_ab[rowbase + x];

    int lane = x & 31, wid = x >> 5;
    #pragma unroll
    for (int o = 1; o < 32; o <<= 1) {
        float ax = __shfl_up_sync(0xffffffffu, v.x, o);
        float ay = __shfl_up_sync(0xffffffffu, v.y, o);
        if (lane >= o) { v.x += ax; v.y += ay; }
    }
    if (lane == 31) wsh[wid] = v;
    __syncthreads();
    if (wid == 0) {
        float2 s = (lane < 16) ? wsh[lane] : make_float2(0.f,0.f);
        #pragma unroll
        for (int o = 1; o < 16; o <<= 1) {
            float ax = __shfl_up_sync(0xffffffffu, s.x, o);
            float ay = __shfl_up_sync(0xffffffffu, s.y, o);
            if (lane >= o) { s.x += ax; s.y += ay; }
        }
        if (lane < 16) wsh[lane] = s;
    }
    __syncthreads();
    if (wid > 0) { float2 off = wsh[wid - 1]; v.x += off.x; v.y += off.y; }
    P[x + 1] = v;
    if (x == 0) P[0] = make_float2(0.f,0.f);
    __syncthreads();

    int lo = x - r, hi = x + r;
    int ai = max(0, lo), bi = min(Wn - 1, hi);
    float2 Pb = P[bi + 1], Pa = P[ai];
    float2 s = make_float2(Pb.x - Pa.x, Pb.y - Pa.y);
    if (lo < 0)      { float2 q = P[-lo + 1], q0 = P[1];               s.x += q.x - q0.x; s.y += q.y - q0.y; }
    if (hi > Wn - 1) { float2 q = P[Wn - 1],  q0 = P[2*Wn - 2 - hi];   s.x += q.x - q0.x; s.y += q.y - q0.y; }
    g_i2[rowbase + x] = s;
}

// ---------------- K4: vertical box for (a,b), 2 cols/thread + t_final + J ----------------
__global__ void k_vbox2f(const float* __restrict__ img,
                         const float* __restrict__ Aa,
                         const int* __restrict__ rp,
                         float* __restrict__ out) {
    int r = clamp_r(rp[0]);
    int k = 2 * r + 1;
    float invk2 = 1.0f / ((float)(k * k));
    int gtid = blockIdx.x * blockDim.x + threadIdx.x;
    int px = gtid & 255;
    int t2 = gtid >> 8;
    int chunk = t2 & (Hn/CH - 1);
    int b = t2 >> 5;
    const float4* __restrict__ base = (const float4*)g_i2 + (b * HWn >> 1) + px;
    const float2* __restrict__ ip = (const float2*)img + (b * 3 * HWn >> 1) + px;
    float2* __restrict__ op = (float2*)out + (b * 3 * HWn >> 1) + px;
    const int RS = Wn / 2;          // row stride in float2/float4 pair units
    const int PS = HWn / 2;         // plane stride
    int y0 = chunk * CH;
    float A0 = Aa[b*3+0], A1 = Aa[b*3+1], A2 = Aa[b*3+2];
    float4 s = make_float4(0.f, 0.f, 0.f, 0.f);
    bool interior = (y0 - r >= 0) && (y0 + r + CH <= Hn - 1);
    if (interior) {
        #pragma unroll 4
        for (int j = -r; j <= r; j++) {
            float4 q = base[(y0 + j) * RS];
            s.x += q.x; s.y += q.y; s.z += q.z; s.w += q.w;
        }
    } else {
        #pragma unroll 4
        for (int j = -r; j <= r; j++) {
            float4 q = base[reflecti(y0 + j, Hn) * RS];
            s.x += q.x; s.y += q.y; s.z += q.z; s.w += q.w;
        }
    }
    #pragma unroll 2
    for (int y = y0; y < y0 + CH; y++) {
        float ma0 = s.x * invk2, mb0 = s.y * invk2;
        float ma1 = s.z * invk2, mb1 = s.w * invk2;
        float2 rv = ip[y * RS];
        float2 gv = ip[PS + y * RS];
        float2 bv = ip[2*PS + y * RS];
        float gray0 = 0.299f * rv.x + 0.587f * gv.x + 0.114f * bv.x;
        float gray1 = 0.299f * rv.y + 0.587f * gv.y + 0.114f * bv.y;
        float t0v = fminf(fmaxf(ma0 * gray0 + mb0, 0.1f), 1.0f);
        float t1v = fminf(fmaxf(ma1 * gray1 + mb1, 0.1f), 1.0f);
        float inv0 = 1.0f / (t0v + 1e-8f);
        float inv1 = 1.0f / (t1v + 1e-8f);
        float2 o0, o1, o2;
        o0.x = fminf(fmaxf((rv.x - A0) * inv0 + A0, 0.f), 1.f);
        o0.y = fminf(fmaxf((rv.y - A0) * inv1 + A0, 0.f), 1.f);
        o1.x = fminf(fmaxf((gv.x - A1) * inv0 + A1, 0.f), 1.f);
        o1.y = fminf(fmaxf((gv.y - A1) * inv1 + A1, 0.f), 1.f);
        o2.x = fminf(fmaxf((bv.x - A2) * inv0 + A2, 0.f), 1.f);
        o2.y = fminf(fmaxf((bv.y - A2) * inv1 + A2, 0.f), 1.f);
        op[y * RS] = o0;
        op[PS + y * RS] = o1;
        op[2*PS + y * RS] = o2;
        float4 qi, qo;
        if (interior) {
            qi = base[(y + r + 1) * RS];
            qo = base[(y - r) * RS];
        } else {
            qi = base[reflecti(y + r + 1, Hn) * RS];
            qo = base[reflecti(y - r, Hn) * RS];
        }
        s.x += qi.x - qo.x; s.y += qi.y - qo.y;
        s.z += qi.z - qo.z; s.w += qi.w - qo.w;
    }
}

// ---------------- histograms & selection (exact radix select on float bits) ----------------
__global__ void k_hist1(const float* __restrict__ J) {
    __shared__ unsigned int h[4096];
    for (int i = threadIdx.x; i < 4096; i += 256) h[i] = 0u;
    __syncthreads();
    int ch = blockIdx.y;
    const float4* p = (const float4*)(J + ch * HWn + blockIdx.x * 8192);
    for (int i = threadIdx.x; i < 2048; i += 256) {
        float4 v = p[i];
        unsigned int b0 = __float_as_uint(v.x) >> 18;
        unsigned int b1 = __float_as_uint(v.y) >> 18;
        unsigned int b2 = __float_as_uint(v.z) >> 18;
        unsigned int b3 = __float_as_uint(v.w) >> 18;
        atomicAdd(&h[min(b0, 4095u)], 1u);
        atomicAdd(&h[min(b1, 4095u)], 1u);
        atomicAdd(&h[min(b2, 4095u)], 1u);
        atomicAdd(&h[min(b3, 4095u)], 1u);
    }
    __syncthreads();
    for (int i = threadIdx.x; i < 4096; i += 256)
        if (h[i]) atomicAdd(&g_h1[ch*4096 + i], h[i]);
}

__global__ void k_sel1(const float* __restrict__ Ll, const float* __restrict__ Lh) {
    __shared__ unsigned int hsh[4096];
    __shared__ unsigned int seg[256];
    int ch = blockIdx.x;
    g_h2[ch*512 + threadIdx.x] = 0u;
    g_h2[ch*512 + 256 + threadIdx.x] = 0u;
    unsigned int ssum = 0u;
    for (int j = 0; j < 16; j++) {
        unsigned int vv = g_h1[ch*4096 + threadIdx.x*16 + j];
        hsh[threadIdx.x*16 + j] = vv;
        ssum += vv;
    }
    seg[threadIdx.x] = ssum;
    __syncthreads();
    if (threadIdx.x == 0) {
        int b = ch / 3;
        for (int w = 0; w < 2; w++) {
            float Lv = (w == 0) ? Ll[b] : Lh[b];
            float fr = (Lv / 100.0f) * 262144.0f;
            int rank = (int)fr;
            if (rank < 0) rank = 0;
            if (rank > HWn - 1) rank = HWn - 1;
            unsigned int cum = 0u;
            int sI = 0;
            while (sI < 255 && cum + seg[sI] <= (unsigned int)rank) { cum += seg[sI]; sI++; }
            int bin = sI * 16;
            while (bin < sI*16 + 15 && cum + hsh[bin] <= (unsigned int)rank) { cum += hsh[bin]; bin++; }
            g_t1[ch*2 + w] = bin;
            g_r1[ch*2 + w] = rank - (int)cum;
        }
    }
}

__global__ void k_hist2(const float* __restrict__ J) {
    __shared__ unsigned int h[512];
    for (int i = threadIdx.x; i < 512; i += 256) h[i] = 0u;
    __syncthreads();
    int ch = blockIdx.y;
    int ta = g_t1[ch*2], tb = g_t1[ch*2 + 1];
    const float4* p = (const float4*)(J + ch * HWn + blockIdx.x * 8192);
    for (int i = threadIdx.x; i < 2048; i += 256) {
        float4 v = p[i];
        unsigned int bb[4] = {__float_as_uint(v.x), __float_as_uint(v.y),
                              __float_as_uint(v.z), __float_as_uint(v.w)};
        #pragma unroll
        for (int j = 0; j < 4; j++) {
            int top = (int)(bb[j] >> 18);
            unsigned int mid = (bb[j] >> 10) & 255u;
            if (top == ta) atomicAdd(&h[mid], 1u);
            if (top == tb) atomicAdd(&h[256 + mid], 1u);
        }
    }
    __syncthreads();
    {
        int i = threadIdx.x;
        if (h[i])       atomicAdd(&g_h2[(ch*2+0)*256 + i], h[i]);
        if (h[256 + i]) atomicAdd(&g_h2[(ch*2+1)*256 + i], h[256 + i]);
    }
}

__global__ void k_sel2() {
    __shared__ unsigned int h[512];
    int ch = blockIdx.x;
    for (int i = 0; i < 8; i++)
        g_h3[ch*2048 + i*256 + threadIdx.x] = 0u;
    h[threadIdx.x]       = g_h2[(ch*2+0)*256 + threadIdx.x];
    h[256 + threadIdx.x] = g_h2[(ch*2+1)*256 + threadIdx.x];
    __syncthreads();
    if (threadIdx.x == 0) {
        for (int w = 0; w < 2; w++) {
            int rem = g_r1[ch*2 + w];
            unsigned int cum = 0u;
            int bin = 0;
            while (bin < 255 && cum + h[w*256 + bin] <= (unsigned int)rem) { cum += h[w*256 + bin]; bin++; }
            g_t22[ch*2 + w] = (g_t1[ch*2 + w] << 8) | bin;
            g_r2[ch*2 + w]  = rem - (int)cum;
        }
    }
}

__global__ void k_hist3(const float* __restrict__ J) {
    __shared__ unsigned int h[2048];
    for (int i = threadIdx.x; i < 2048; i += 256) h[i] = 0u;
    __syncthreads();
    int ch = blockIdx.y;
    int ta = g_t22[ch*2], tb = g_t22[ch*2 + 1];
    const float4* p = (const float4*)(J + ch * HWn + blockIdx.x * 8192);
    for (int i = threadIdx.x; i < 2048; i += 256) {
        float4 v = p[i];
        unsigned int bb[4] = {__float_as_uint(v.x), __float_as_uint(v.y),
                              __float_as_uint(v.z), __float_as_uint(v.w)};
        #pragma unroll
        for (int j = 0; j < 4; j++) {
            int top = (int)(bb[j] >> 10);
            unsigned int lo = bb[j] & 1023u;
            if (top == ta) atomicAdd(&h[lo], 1u);
            if (top == tb) atomicAdd(&h[1024 + lo], 1u);
        }
    }
    __syncthreads();
    for (int i = threadIdx.x; i < 2048; i += 256)
        if (h[i]) atomicAdd(&g_h3[ch*2048 + i], h[i]);
}

__global__ void k_sel3() {
    __shared__ unsigned int h[2048];
    int ch = blockIdx.x;
    for (int i = threadIdx.x; i < 2048; i += 256) h[i] = g_h3[ch*2048 + i];
    __syncthreads();
    if (threadIdx.x == 0) {
        for (int w = 0; w < 2; w++) {
            int rem = g_r2[ch*2 + w];
            unsigned int cum = 0u;
            int bin = 0;
            while (bin < 1023 && cum + h[w*1024 + bin] <= (unsigned int)rem) { cum += h[w*1024 + bin]; bin++; }
            unsigned int bits = ((unsigned int)g_t22[ch*2 + w] << 10) | (unsigned int)bin;
            float pv = __uint_as_float(bits);
            if (w == 0) g_pl[ch] = pv; else g_ph[ch] = pv;
        }
    }
}

// ---------------- final normalize (in place on d_out), float4 ----------------
__global__ void k_final(float* __restrict__ out) {
    int i = blockIdx.x * blockDim.x + threadIdx.x;   // float4 index
    if (i >= 3 * BHWn / 4) return;
    int ch = i >> 16;            // (i*4) >> 18
    float pl = g_pl[ch], ph = g_ph[ch];
    float inv = 1.0f / (ph - pl + 1e-8f);
    float4 v = ((float4*)out)[i];
    v.x = fminf(fmaxf((fminf(fmaxf(v.x, pl), ph) - pl) * inv, 0.f), 1.f);
    v.y = fminf(fmaxf((fminf(fmaxf(v.y, pl), ph) - pl) * inv, 0.f), 1.f);
    v.z = fminf(fmaxf((fminf(fmaxf(v.z, pl), ph) - pl) * inv, 0.f), 1.f);
    v.w = fminf(fmaxf((fminf(fmaxf(v.w, pl), ph) - pl) * inv, 0.f), 1.f);
    ((float4*)out)[i] = v;
}

// ---------------- launch ----------------
extern "C" void kernel_launch(void* const* d_in, const int* in_sizes, int n_in,
                              void* d_out, int out_size) {
    const float* img   = (const float*)d_in[0];
    const float* omega = (const float*)d_in[1];
    const float* A     = (const float*)d_in[2];
    const float* Ll    = (const float*)d_in[3];
    const float* Lh    = (const float*)d_in[4];
    const int*   rp    = (const int*)d_in[5];
    float* out = (float*)d_out;

    int nvthreads = Bn * (Wn/2) * (Hn/CH);   // 65536

    k_hbox4 <<<Bn*Hn, 512>>>(img, omega, A, rp);
    k_vbox4 <<<nvthreads/128, 128>>>(rp);
    k_hbox2 <<<Bn*Hn, 512>>>(rp);
    k_vbox2f<<<nvthreads/128, 128>>>(img, A, rp, out);
    k_hist1 <<<dim3(32, NCH), 256>>>(out);
    k_sel1  <<<NCH, 256>>>(Ll, Lh);
    k_hist2 <<<dim3(32, NCH), 256>>>(out);
    k_sel2  <<<NCH, 256>>>();
    k_hist3 <<<dim3(32, NCH), 256>>>(out);
    k_sel3  <<<NCH, 256>>>();
    k_final <<<(3*BHWn/4 + 255)/256, 256>>>(out);
}

// round 4
// speedup vs baseline: 1.9561x; 1.0479x over previous
#include <cuda_runtime.h>
#include <math.h>

#define Bn   8
#define Hn   512
#define Wn   512
#define HWn  (Hn*Wn)      // 262144 = 2^18
#define BHWn (Bn*HWn)     // 2097152
#define NCH  24           // B*3 channels for percentile
#define CH   8            // rows per thread in vertical kernels

// ---------------- scratch (static device globals; no allocation) ----------------
__device__ float4 g_i4[BHWn];    // H-pass sums of (gray, tg, gray*tg, gray*gray)
__device__ float2 g_ab[BHWn];    // (a, b) guided filter coefficients
__device__ float2 g_i2[BHWn];    // H-pass sums of (a, b)
__device__ unsigned int g_h1[NCH*4096];
__device__ unsigned int g_h2[NCH*2*256];
__device__ unsigned int g_h3[NCH*2*1024];
__device__ int   g_t1[NCH*2];
__device__ int   g_r1[NCH*2];
__device__ int   g_t22[NCH*2];
__device__ int   g_r2[NCH*2];
__device__ float g_pl[NCH];
__device__ float g_ph[NCH];

__device__ __forceinline__ int reflecti(int i, int n) {
    if (i < 0) i = -i;
    if (i > n - 1) i = 2 * (n - 1) - i;
    return i;
}
__device__ __forceinline__ int clamp_r(int r) {
    if (r < 1) r = 1;
    if (r > 50) r = 50;
    return r;
}

// ---------------- K1: fused t0/gray/tg + horizontal box (4 planes) ----------------
__global__ void k_hbox4(const float* __restrict__ img,
                        const float* __restrict__ omega,
                        const float* __restrict__ Aa,
                        const int* __restrict__ rp) {
    int r = clamp_r(rp[0]);
    __shared__ float4 P[Wn + 1];
    __shared__ float4 wsh[16];
    __shared__ float t0s[Wn];
    int x = threadIdx.x;               // 512 threads
    int rowid = blockIdx.x;            // B*H rows
    int b = rowid >> 9, y = rowid & 511;
    int ys = (y == 0) ? 0 : y - 1;

    // zero g_h1 for the later hist pass (4096 blocks * 24 = 98304 entries)
    if (x < NCH) g_h1[rowid * NCH + x] = 0u;

    const float* ib = img + b * 3 * HWn;
    float a0 = Aa[b*3+0] + 1e-8f;
    float a1 = Aa[b*3+1] + 1e-8f;
    float a2 = Aa[b*3+2] + 1e-8f;
    float om = omega[b];

    float rv = ib[y*Wn + x];
    float gv = ib[HWn + y*Wn + x];
    float bv = ib[2*HWn + y*Wn + x];
    float t0y = 1.0f - om * fminf(fminf(rv/a0, gv/a1), bv/a2);
    float t0yv;
    if (ys == y) {
        t0yv = t0y;
    } else {
        float rs = ib[ys*Wn + x];
        float gs = ib[HWn + ys*Wn + x];
        float bs = ib[2*HWn + ys*Wn + x];
        t0yv = 1.0f - om * fminf(fminf(rs/a0, gs/a1), bs/a2);
    }
    t0s[x] = t0yv;
    float gray = 0.299f * rv + 0.587f * gv + 0.114f * bv;
    __syncthreads();

    float txv;
    if (x == 0) {
        txv = t0s[0];
    } else {
        float tp = t0s[x - 1];
        txv = tp * __expf(-fabsf(t0yv - tp));
    }
    float tgv = txv * __expf(-fabsf(t0y - t0yv));

    float4 v = make_float4(gray, tgv, gray * tgv, gray * gray);

    int lane = x & 31, wid = x >> 5;
    #pragma unroll
    for (int o = 1; o < 32; o <<= 1) {
        float ax = __shfl_up_sync(0xffffffffu, v.x, o);
        float ay = __shfl_up_sync(0xffffffffu, v.y, o);
        float az = __shfl_up_sync(0xffffffffu, v.z, o);
        float aw = __shfl_up_sync(0xffffffffu, v.w, o);
        if (lane >= o) { v.x += ax; v.y += ay; v.z += az; v.w += aw; }
    }
    if (lane == 31) wsh[wid] = v;
    __syncthreads();
    if (wid == 0) {
        float4 s = (lane < 16) ? wsh[lane] : make_float4(0.f,0.f,0.f,0.f);
        #pragma unroll
        for (int o = 1; o < 16; o <<= 1) {
            float ax = __shfl_up_sync(0xffffffffu, s.x, o);
            float ay = __shfl_up_sync(0xffffffffu, s.y, o);
            float az = __shfl_up_sync(0xffffffffu, s.z, o);
            float aw = __shfl_up_sync(0xffffffffu, s.w, o);
            if (lane >= o) { s.x += ax; s.y += ay; s.z += az; s.w += aw; }
        }
        if (lane < 16) wsh[lane] = s;
    }
    __syncthreads();
    if (wid > 0) {
        float4 off = wsh[wid - 1];
        v.x += off.x; v.y += off.y; v.z += off.z; v.w += off.w;
    }
    P[x + 1] = v;
    if (x == 0) P[0] = make_float4(0.f,0.f,0.f,0.f);
    __syncthreads();

    int lo = x - r, hi = x + r;
    int ai = max(0, lo), bi = min(Wn - 1, hi);
    float4 Pb = P[bi + 1], Pa = P[ai];
    float4 s = make_float4(Pb.x - Pa.x, Pb.y - Pa.y, Pb.z - Pa.z, Pb.w - Pa.w);
    if (lo < 0) {
        float4 q  = P[-lo + 1], q0 = P[1];
        s.x += q.x - q0.x; s.y += q.y - q0.y; s.z += q.z - q0.z; s.w += q.w - q0.w;
    }
    if (hi > Wn - 1) {
        float4 q  = P[Wn - 1], q0 = P[2 * Wn - 2 - hi];
        s.x += q.x - q0.x; s.y += q.y - q0.y; s.z += q.z - q0.z; s.w += q.w - q0.w;
    }
    g_i4[rowid * Wn + x] = s;
}

// ---------------- K2: vertical box (sliding), 2 columns/thread + a,b ----------------
__global__ void k_vbox4(const int* __restrict__ rp) {
    int r = clamp_r(rp[0]);
    int k = 2 * r + 1;
    float invk2 = 1.0f / ((float)(k * k));
    int gtid = blockIdx.x * blockDim.x + threadIdx.x;
    int px = gtid & 255;                // column pair 0..255
    int t2 = gtid >> 8;
    int chunk = t2 & (Hn/CH - 1);
    int b = t2 / (Hn/CH);
    const float4* __restrict__ base = g_i4 + b * HWn + px * 2;
    float4* __restrict__ gab4 = (float4*)g_ab + (b * HWn >> 1) + px;
    int y0 = chunk * CH;
    float4 s0 = make_float4(0.f,0.f,0.f,0.f);
    float4 s1 = make_float4(0.f,0.f,0.f,0.f);
    if (y0 - r >= 0 && y0 + r + CH <= Hn - 1) {
        #pragma unroll 4
        for (int j = -r; j <= r; j++) {
            float4 q0 = base[(y0 + j) * Wn];
            float4 q1 = base[(y0 + j) * Wn + 1];
            s0.x += q0.x; s0.y += q0.y; s0.z += q0.z; s0.w += q0.w;
            s1.x += q1.x; s1.y += q1.y; s1.z += q1.z; s1.w += q1.w;
        }
        #pragma unroll
        for (int y = y0; y < y0 + CH; y++) {
            float mI0  = s0.x * invk2, mp0  = s0.y * invk2;
            float mIp0 = s0.z * invk2, mII0 = s0.w * invk2;
            float a0 = (mIp0 - mI0 * mp0) / ((mII0 - mI0 * mI0) + 0.5f);
            float mI1  = s1.x * invk2, mp1  = s1.y * invk2;
            float mIp1 = s1.z * invk2, mII1 = s1.w * invk2;
            float a1 = (mIp1 - mI1 * mp1) / ((mII1 - mI1 * mI1) + 0.5f);
            gab4[y * (Wn/2)] = make_float4(a0, mp0 - a0 * mI0, a1, mp1 - a1 * mI1);
            float4 qi0 = base[(y + r + 1) * Wn];
            float4 qi1 = base[(y + r + 1) * Wn + 1];
            float4 qo0 = base[(y - r) * Wn];
            float4 qo1 = base[(y - r) * Wn + 1];
            s0.x += qi0.x - qo0.x; s0.y += qi0.y - qo0.y;
            s0.z += qi0.z - qo0.z; s0.w += qi0.w - qo0.w;
            s1.x += qi1.x - qo1.x; s1.y += qi1.y - qo1.y;
            s1.z += qi1.z - qo1.z; s1.w += qi1.w - qo1.w;
        }
    } else {
        #pragma unroll 4
        for (int j = -r; j <= r; j++) {
            int yy = reflecti(y0 + j, Hn);
            float4 q0 = base[yy * Wn];
            float4 q1 = base[yy * Wn + 1];
            s0.x += q0.x; s0.y += q0.y; s0.z += q0.z; s0.w += q0.w;
            s1.x += q1.x; s1.y += q1.y; s1.z += q1.z; s1.w += q1.w;
        }
        #pragma unroll
        for (int y = y0; y < y0 + CH; y++) {
            float mI0  = s0.x * invk2, mp0  = s0.y * invk2;
            float mIp0 = s0.z * invk2, mII0 = s0.w * invk2;
            float a0 = (mIp0 - mI0 * mp0) / ((mII0 - mI0 * mI0) + 0.5f);
            float mI1  = s1.x * invk2, mp1  = s1.y * invk2;
            float mIp1 = s1.z * invk2, mII1 = s1.w * invk2;
            float a1 = (mIp1 - mI1 * mp1) / ((mII1 - mI1 * mI1) + 0.5f);
            gab4[y * (Wn/2)] = make_float4(a0, mp0 - a0 * mI0, a1, mp1 - a1 * mI1);
            int yi = reflecti(y + r + 1, Hn), yo = reflecti(y - r, Hn);
            float4 qi0 = base[yi * Wn];
            float4 qi1 = base[yi * Wn + 1];
            float4 qo0 = base[yo * Wn];
            float4 qo1 = base[yo * Wn + 1];
            s0.x += qi0.x - qo0.x; s0.y += qi0.y - qo0.y;
            s0.z += qi0.z - qo0.z; s0.w += qi0.w - qo0.w;
            s1.x += qi1.x - qo1.x; s1.y += qi1.y - qo1.y;
            s1.z += qi1.z - qo1.z; s1.w += qi1.w - qo1.w;
        }
    }
}

// ---------------- K3: horizontal box for (a,b) ----------------
__global__ void k_hbox2(const int* __restrict__ rp) {
    int r = clamp_r(rp[0]);
    __shared__ float2 P[Wn + 1];
    __shared__ float2 wsh[16];
    int x = threadIdx.x;
    int rowbase = blockIdx.x * Wn;
    float2 v = g_ab[rowbase + x];

    int lane = x & 31, wid = x >> 5;
    #pragma unroll
    for (int o = 1; o < 32; o <<= 1) {
        float ax = __shfl_up_sync(0xffffffffu, v.x, o);
        float ay = __shfl_up_sync(0xffffffffu, v.y, o);
        if (lane >= o) { v.x += ax; v.y += ay; }
    }
    if (lane == 31) wsh[wid] = v;
    __syncthreads();
    if (wid == 0) {
        float2 s = (lane < 16) ? wsh[lane] : make_float2(0.f,0.f);
        #pragma unroll
        for (int o = 1; o < 16; o <<= 1) {
            float ax = __shfl_up_sync(0xffffffffu, s.x, o);
            float ay = __shfl_up_sync(0xffffffffu, s.y, o);
            if (lane >= o) { s.x += ax; s.y += ay; }
        }
        if (lane < 16) wsh[lane] = s;
    }
    __syncthreads();
    if (wid > 0) { float2 off = wsh[wid - 1]; v.x += off.x; v.y += off.y; }
    P[x + 1] = v;
    if (x == 0) P[0] = make_float2(0.f,0.f);
    __syncthreads();

    int lo = x - r, hi = x + r;
    int ai = max(0, lo), bi = min(Wn - 1, hi);
    float2 Pb = P[bi + 1], Pa = P[ai];
    float2 s = make_float2(Pb.x - Pa.x, Pb.y - Pa.y);
    if (lo < 0)      { float2 q = P[-lo + 1], q0 = P[1];               s.x += q.x - q0.x; s.y += q.y - q0.y; }
    if (hi > Wn - 1) { float2 q = P[Wn - 1],  q0 = P[2*Wn - 2 - hi];   s.x += q.x - q0.x; s.y += q.y - q0.y; }
    g_i2[rowbase + x] = s;
}

// ---------------- K4: vertical box for (a,b), 2 cols/thread + t_final + J ----------------
__global__ void k_vbox2f(const float* __restrict__ img,
                         const float* __restrict__ Aa,
                         const int* __restrict__ rp,
                         float* __restrict__ out) {
    int r = clamp_r(rp[0]);
    int k = 2 * r + 1;
    float invk2 = 1.0f / ((float)(k * k));
    int gtid = blockIdx.x * blockDim.x + threadIdx.x;
    int px = gtid & 255;
    int t2 = gtid >> 8;
    int chunk = t2 & (Hn/CH - 1);
    int b = t2 / (Hn/CH);
    const float4* __restrict__ base = (const float4*)g_i2 + (b * HWn >> 1) + px;
    const float2* __restrict__ ip = (const float2*)img + (b * 3 * HWn >> 1) + px;
    float2* __restrict__ op = (float2*)out + (b * 3 * HWn >> 1) + px;
    const int RS = Wn / 2;          // row stride in float2/float4 pair units
    const int PS = HWn / 2;         // plane stride
    int y0 = chunk * CH;
    float A0 = Aa[b*3+0], A1 = Aa[b*3+1], A2 = Aa[b*3+2];
    float4 s = make_float4(0.f, 0.f, 0.f, 0.f);
    bool interior = (y0 - r >= 0) && (y0 + r + CH <= Hn - 1);
    if (interior) {
        #pragma unroll 4
        for (int j = -r; j <= r; j++) {
            float4 q = base[(y0 + j) * RS];
            s.x += q.x; s.y += q.y; s.z += q.z; s.w += q.w;
        }
    } else {
        #pragma unroll 4
        for (int j = -r; j <= r; j++) {
            float4 q = base[reflecti(y0 + j, Hn) * RS];
            s.x += q.x; s.y += q.y; s.z += q.z; s.w += q.w;
        }
    }
    #pragma unroll
    for (int y = y0; y < y0 + CH; y++) {
        float ma0 = s.x * invk2, mb0 = s.y * invk2;
        float ma1 = s.z * invk2, mb1 = s.w * invk2;
        float2 rv = ip[y * RS];
        float2 gv = ip[PS + y * RS];
        float2 bv = ip[2*PS + y * RS];
        float gray0 = 0.299f * rv.x + 0.587f * gv.x + 0.114f * bv.x;
        float gray1 = 0.299f * rv.y + 0.587f * gv.y + 0.114f * bv.y;
        float t0v = fminf(fmaxf(ma0 * gray0 + mb0, 0.1f), 1.0f);
        float t1v = fminf(fmaxf(ma1 * gray1 + mb1, 0.1f), 1.0f);
        float inv0 = 1.0f / (t0v + 1e-8f);
        float inv1 = 1.0f / (t1v + 1e-8f);
        float2 o0, o1, o2;
        o0.x = fminf(fmaxf((rv.x - A0) * inv0 + A0, 0.f), 1.f);
        o0.y = fminf(fmaxf((rv.y - A0) * inv1 + A0, 0.f), 1.f);
        o1.x = fminf(fmaxf((gv.x - A1) * inv0 + A1, 0.f), 1.f);
        o1.y = fminf(fmaxf((gv.y - A1) * inv1 + A1, 0.f), 1.f);
        o2.x = fminf(fmaxf((bv.x - A2) * inv0 + A2, 0.f), 1.f);
        o2.y = fminf(fmaxf((bv.y - A2) * inv1 + A2, 0.f), 1.f);
        op[y * RS] = o0;
        op[PS + y * RS] = o1;
        op[2*PS + y * RS] = o2;
        float4 qi, qo;
        if (interior) {
            qi = base[(y + r + 1) * RS];
            qo = base[(y - r) * RS];
        } else {
            qi = base[reflecti(y + r + 1, Hn) * RS];
            qo = base[reflecti(y - r, Hn) * RS];
        }
        s.x += qi.x - qo.x; s.y += qi.y - qo.y;
        s.z += qi.z - qo.z; s.w += qi.w - qo.w;
    }
}

// ---------------- histograms & selection (exact radix select on float bits) ----------------
__global__ void k_hist1(const float* __restrict__ J) {
    __shared__ unsigned int h[4096];
    for (int i = threadIdx.x; i < 4096; i += 256) h[i] = 0u;
    __syncthreads();
    int ch = blockIdx.y;
    const float4* p = (const float4*)(J + ch * HWn + blockIdx.x * 8192);
    for (int i = threadIdx.x; i < 2048; i += 256) {
        float4 v = p[i];
        unsigned int b0 = __float_as_uint(v.x) >> 18;
        unsigned int b1 = __float_as_uint(v.y) >> 18;
        unsigned int b2 = __float_as_uint(v.z) >> 18;
        unsigned int b3 = __float_as_uint(v.w) >> 18;
        atomicAdd(&h[min(b0, 4095u)], 1u);
        atomicAdd(&h[min(b1, 4095u)], 1u);
        atomicAdd(&h[min(b2, 4095u)], 1u);
        atomicAdd(&h[min(b3, 4095u)], 1u);
    }
    __syncthreads();
    for (int i = threadIdx.x; i < 4096; i += 256)
        if (h[i]) atomicAdd(&g_h1[ch*4096 + i], h[i]);
}

__global__ void k_sel1(const float* __restrict__ Ll, const float* __restrict__ Lh) {
    __shared__ unsigned int hsh[4096];
    __shared__ unsigned int seg[256];
    int ch = blockIdx.x;
    g_h2[ch*512 + threadIdx.x] = 0u;
    g_h2[ch*512 + 256 + threadIdx.x] = 0u;
    unsigned int ssum = 0u;
    for (int j = 0; j < 16; j++) {
        unsigned int vv = g_h1[ch*4096 + threadIdx.x*16 + j];
        hsh[threadIdx.x*16 + j] = vv;
        ssum += vv;
    }
    seg[threadIdx.x] = ssum;
    __syncthreads();
    if (threadIdx.x == 0) {
        int b = ch / 3;
        for (int w = 0; w < 2; w++) {
            float Lv = (w == 0) ? Ll[b] : Lh[b];
            float fr = (Lv / 100.0f) * 262144.0f;
            int rank = (int)fr;
            if (rank < 0) rank = 0;
            if (rank > HWn - 1) rank = HWn - 1;
            unsigned int cum = 0u;
            int sI = 0;
            while (sI < 255 && cum + seg[sI] <= (unsigned int)rank) { cum += seg[sI]; sI++; }
            int bin = sI * 16;
            while (bin < sI*16 + 15 && cum + hsh[bin] <= (unsigned int)rank) { cum += hsh[bin]; bin++; }
            g_t1[ch*2 + w] = bin;
            g_r1[ch*2 + w] = rank - (int)cum;
        }
    }
}

__global__ void k_hist2(const float* __restrict__ J) {
    __shared__ unsigned int h[512];
    for (int i = threadIdx.x; i < 512; i += 256) h[i] = 0u;
    __syncthreads();
    int ch = blockIdx.y;
    int ta = g_t1[ch*2], tb = g_t1[ch*2 + 1];
    const float4* p = (const float4*)(J + ch * HWn + blockIdx.x * 8192);
    for (int i = threadIdx.x; i < 2048; i += 256) {
        float4 v = p[i];
        unsigned int bb[4] = {__float_as_uint(v.x), __float_as_uint(v.y),
                              __float_as_uint(v.z), __float_as_uint(v.w)};
        #pragma unroll
        for (int j = 0; j < 4; j++) {
            int top = (int)(bb[j] >> 18);
            unsigned int mid = (bb[j] >> 10) & 255u;
            if (top == ta) atomicAdd(&h[mid], 1u);
            if (top == tb) atomicAdd(&h[256 + mid], 1u);
        }
    }
    __syncthreads();
    {
        int i = threadIdx.x;
        if (h[i])       atomicAdd(&g_h2[(ch*2+0)*256 + i], h[i]);
        if (h[256 + i]) atomicAdd(&g_h2[(ch*2+1)*256 + i], h[256 + i]);
    }
}

__global__ void k_sel2() {
    __shared__ unsigned int h[512];
    int ch = blockIdx.x;
    for (int i = 0; i < 8; i++)
        g_h3[ch*2048 + i*256 + threadIdx.x] = 0u;
    h[threadIdx.x]       = g_h2[(ch*2+0)*256 + threadIdx.x];
    h[256 + threadIdx.x] = g_h2[(ch*2+1)*256 + threadIdx.x];
    __syncthreads();
    if (threadIdx.x == 0) {
        for (int w = 0; w < 2; w++) {
            int rem = g_r1[ch*2 + w];
            unsigned int cum = 0u;
            int bin = 0;
            while (bin < 255 && cum + h[w*256 + bin] <= (unsigned int)rem) { cum += h[w*256 + bin]; bin++; }
            g_t22[ch*2 + w] = (g_t1[ch*2 + w] << 8) | bin;
            g_r2[ch*2 + w]  = rem - (int)cum;
        }
    }
}

__global__ void k_hist3(const float* __restrict__ J) {
    __shared__ unsigned int h[2048];
    for (int i = threadIdx.x; i < 2048; i += 256) h[i] = 0u;
    __syncthreads();
    int ch = blockIdx.y;
    int ta = g_t22[ch*2], tb = g_t22[ch*2 + 1];
    const float4* p = (const float4*)(J + ch * HWn + blockIdx.x * 8192);
    for (int i = threadIdx.x; i < 2048; i += 256) {
        float4 v = p[i];
        unsigned int bb[4] = {__float_as_uint(v.x), __float_as_uint(v.y),
                              __float_as_uint(v.z), __float_as_uint(v.w)};
        #pragma unroll
        for (int j = 0; j < 4; j++) {
            int top = (int)(bb[j] >> 10);
            unsigned int lo = bb[j] & 1023u;
            if (top == ta) atomicAdd(&h[lo], 1u);
            if (top == tb) atomicAdd(&h[1024 + lo], 1u);
        }
    }
    __syncthreads();
    for (int i = threadIdx.x; i < 2048; i += 256)
        if (h[i]) atomicAdd(&g_h3[ch*2048 + i], h[i]);
}

__global__ void k_sel3() {
    __shared__ unsigned int h[2048];
    int ch = blockIdx.x;
    for (int i = threadIdx.x; i < 2048; i += 256) h[i] = g_h3[ch*2048 + i];
    __syncthreads();
    if (threadIdx.x == 0) {
        for (int w = 0; w < 2; w++) {
            int rem = g_r2[ch*2 + w];
            unsigned int cum = 0u;
            int bin = 0;
            while (bin < 1023 && cum + h[w*1024 + bin] <= (unsigned int)rem) { cum += h[w*1024 + bin]; bin++; }
            unsigned int bits = ((unsigned int)g_t22[ch*2 + w] << 10) | (unsigned int)bin;
            float pv = __uint_as_float(bits);
            if (w == 0) g_pl[ch] = pv; else g_ph[ch] = pv;
        }
    }
}

// ---------------- final normalize (in place on d_out), float4 ----------------
__global__ void k_final(float* __restrict__ out) {
    int i = blockIdx.x * blockDim.x + threadIdx.x;   // float4 index
    if (i >= 3 * BHWn / 4) return;
    int ch = i >> 16;            // (i*4) >> 18
    float pl = g_pl[ch], ph = g_ph[ch];
    float inv = 1.0f / (ph - pl + 1e-8f);
    float4 v = ((float4*)out)[i];
    v.x = fminf(fmaxf((fminf(fmaxf(v.x, pl), ph) - pl) * inv, 0.f), 1.f);
    v.y = fminf(fmaxf((fminf(fmaxf(v.y, pl), ph) - pl) * inv, 0.f), 1.f);
    v.z = fminf(fmaxf((fminf(fmaxf(v.z, pl), ph) - pl) * inv, 0.f), 1.f);
    v.w = fminf(fmaxf((fminf(fmaxf(v.w, pl), ph) - pl) * inv, 0.f), 1.f);
    ((float4*)out)[i] = v;
}

// ---------------- launch ----------------
extern "C" void kernel_launch(void* const* d_in, const int* in_sizes, int n_in,
                              void* d_out, int out_size) {
    const float* img   = (const float*)d_in[0];
    const float* omega = (const float*)d_in[1];
    const float* A     = (const float*)d_in[2];
    const float* Ll    = (const float*)d_in[3];
    const float* Lh    = (const float*)d_in[4];
    const int*   rp    = (const int*)d_in[5];
    float* out = (float*)d_out;

    int nvthreads = Bn * (Wn/2) * (Hn/CH);   // 131072

    k_hbox4 <<<Bn*Hn, 512>>>(img, omega, A, rp);
    k_vbox4 <<<nvthreads/128, 128>>>(rp);
    k_hbox2 <<<Bn*Hn, 512>>>(rp);
    k_vbox2f<<<nvthreads/128, 128>>>(img, A, rp, out);
    k_hist1 <<<dim3(32, NCH), 256>>>(out);
    k_sel1  <<<NCH, 256>>>(Ll, Lh);
    k_hist2 <<<dim3(32, NCH), 256>>>(out);
    k_sel2  <<<NCH, 256>>>();
    k_hist3 <<<dim3(32, NCH), 256>>>(out);
    k_sel3  <<<NCH, 256>>>();
    k_final <<<(3*BHWn/4 + 255)/256, 256>>>(out);
}

// round 5
// speedup vs baseline: 2.2317x; 1.1409x over previous
#include <cuda_runtime.h>
#include <math.h>

#define Bn   8
#define Hn   512
#define Wn   512
#define HWn  (Hn*Wn)      // 262144 = 2^18
#define BHWn (Bn*HWn)     // 2097152
#define NCH  24           // B*3 channels for percentile
#define CH   4            // rows per thread in vertical kernels

// ---------------- scratch (static device globals; no allocation) ----------------
__device__ float4 g_i4[BHWn];    // H-pass sums of (gray, tg, gray*tg, gray*gray)
__device__ float2 g_ab[BHWn];    // (a, b) guided filter coefficients
__device__ float2 g_i2[BHWn];    // H-pass sums of (a, b)
__device__ unsigned int g_h1[NCH*4096];
__device__ unsigned int g_h2[NCH*2*4096];
__device__ int   g_t1[NCH*2];
__device__ int   g_r1[NCH*2];
__device__ float g_pl[NCH];
__device__ float g_ph[NCH];

__device__ __forceinline__ int reflecti(int i, int n) {
    if (i < 0) i = -i;
    if (i > n - 1) i = 2 * (n - 1) - i;
    return i;
}
__device__ __forceinline__ int clamp_r(int r) {
    if (r < 1) r = 1;
    if (r > 50) r = 50;
    return r;
}

// ---------------- K1: fused t0/gray/tg + horizontal box (4 planes) ----------------
__global__ void k_hbox4(const float* __restrict__ img,
                        const float* __restrict__ omega,
                        const float* __restrict__ Aa,
                        const int* __restrict__ rp) {
    int r = clamp_r(rp[0]);
    __shared__ float4 P[Wn + 1];
    __shared__ float4 wsh[16];
    __shared__ float t0s[Wn];
    int x = threadIdx.x;               // 512 threads
    int rowid = blockIdx.x;            // B*H rows
    int b = rowid >> 9, y = rowid & 511;
    int ys = (y == 0) ? 0 : y - 1;

    // zero g_h1 for the later hist pass (4096 blocks * 24 = 98304 entries)
    if (x < NCH) g_h1[rowid * NCH + x] = 0u;

    const float* ib = img + b * 3 * HWn;
    float a0 = Aa[b*3+0] + 1e-8f;
    float a1 = Aa[b*3+1] + 1e-8f;
    float a2 = Aa[b*3+2] + 1e-8f;
    float om = omega[b];

    float rv = ib[y*Wn + x];
    float gv = ib[HWn + y*Wn + x];
    float bv = ib[2*HWn + y*Wn + x];
    float t0y = 1.0f - om * fminf(fminf(rv/a0, gv/a1), bv/a2);
    float t0yv;
    if (ys == y) {
        t0yv = t0y;
    } else {
        float rs = ib[ys*Wn + x];
        float gs = ib[HWn + ys*Wn + x];
        float bs = ib[2*HWn + ys*Wn + x];
        t0yv = 1.0f - om * fminf(fminf(rs/a0, gs/a1), bs/a2);
    }
    t0s[x] = t0yv;
    float gray = 0.299f * rv + 0.587f * gv + 0.114f * bv;
    __syncthreads();

    float txv;
    if (x == 0) {
        txv = t0s[0];
    } else {
        float tp = t0s[x - 1];
        txv = tp * __expf(-fabsf(t0yv - tp));
    }
    float tgv = txv * __expf(-fabsf(t0y - t0yv));

    float4 v = make_float4(gray, tgv, gray * tgv, gray * gray);

    int lane = x & 31, wid = x >> 5;
    #pragma unroll
    for (int o = 1; o < 32; o <<= 1) {
        float ax = __shfl_up_sync(0xffffffffu, v.x, o);
        float ay = __shfl_up_sync(0xffffffffu, v.y, o);
        float az = __shfl_up_sync(0xffffffffu, v.z, o);
        float aw = __shfl_up_sync(0xffffffffu, v.w, o);
        if (lane >= o) { v.x += ax; v.y += ay; v.z += az; v.w += aw; }
    }
    if (lane == 31) wsh[wid] = v;
    __syncthreads();
    if (wid == 0) {
        float4 s = (lane < 16) ? wsh[lane] : make_float4(0.f,0.f,0.f,0.f);
        #pragma unroll
        for (int o = 1; o < 16; o <<= 1) {
            float ax = __shfl_up_sync(0xffffffffu, s.x, o);
            float ay = __shfl_up_sync(0xffffffffu, s.y, o);
            float az = __shfl_up_sync(0xffffffffu, s.z, o);
            float aw = __shfl_up_sync(0xffffffffu, s.w, o);
            if (lane >= o) { s.x += ax; s.y += ay; s.z += az; s.w += aw; }
        }
        if (lane < 16) wsh[lane] = s;
    }
    __syncthreads();
    if (wid > 0) {
        float4 off = wsh[wid - 1];
        v.x += off.x; v.y += off.y; v.z += off.z; v.w += off.w;
    }
    P[x + 1] = v;
    if (x == 0) P[0] = make_float4(0.f,0.f,0.f,0.f);
    __syncthreads();

    int lo = x - r, hi = x + r;
    int ai = max(0, lo), bi = min(Wn - 1, hi);
    float4 Pb = P[bi + 1], Pa = P[ai];
    float4 s = make_float4(Pb.x - Pa.x, Pb.y - Pa.y, Pb.z - Pa.z, Pb.w - Pa.w);
    if (lo < 0) {
        float4 q  = P[-lo + 1], q0 = P[1];
        s.x += q.x - q0.x; s.y += q.y - q0.y; s.z += q.z - q0.z; s.w += q.w - q0.w;
    }
    if (hi > Wn - 1) {
        float4 q  = P[Wn - 1], q0 = P[2 * Wn - 2 - hi];
        s.x += q.x - q0.x; s.y += q.y - q0.y; s.z += q.z - q0.z; s.w += q.w - q0.w;
    }
    g_i4[rowid * Wn + x] = s;
}

// ---------------- K2: vertical box (sliding), 2 columns/thread + a,b ----------------
__global__ void k_vbox4(const int* __restrict__ rp) {
    int r = clamp_r(rp[0]);
    int k = 2 * r + 1;
    float invk2 = 1.0f / ((float)(k * k));
    int gtid = blockIdx.x * blockDim.x + threadIdx.x;
    int px = gtid & 255;                // column pair 0..255
    int t2 = gtid >> 8;
    int chunk = t2 & (Hn/CH - 1);
    int b = t2 / (Hn/CH);
    const float4* __restrict__ base = g_i4 + b * HWn + px * 2;
    float4* __restrict__ gab4 = (float4*)g_ab + (b * HWn >> 1) + px;
    int y0 = chunk * CH;
    float4 s0 = make_float4(0.f,0.f,0.f,0.f);
    float4 s1 = make_float4(0.f,0.f,0.f,0.f);
    if (y0 - r >= 0 && y0 + r + CH <= Hn - 1) {
        #pragma unroll 4
        for (int j = -r; j <= r; j++) {
            float4 q0 = base[(y0 + j) * Wn];
            float4 q1 = base[(y0 + j) * Wn + 1];
            s0.x += q0.x; s0.y += q0.y; s0.z += q0.z; s0.w += q0.w;
            s1.x += q1.x; s1.y += q1.y; s1.z += q1.z; s1.w += q1.w;
        }
        #pragma unroll
        for (int y = y0; y < y0 + CH; y++) {
            float mI0  = s0.x * invk2, mp0  = s0.y * invk2;
            float mIp0 = s0.z * invk2, mII0 = s0.w * invk2;
            float a0 = (mIp0 - mI0 * mp0) / ((mII0 - mI0 * mI0) + 0.5f);
            float mI1  = s1.x * invk2, mp1  = s1.y * invk2;
            float mIp1 = s1.z * invk2, mII1 = s1.w * invk2;
            float a1 = (mIp1 - mI1 * mp1) / ((mII1 - mI1 * mI1) + 0.5f);
            gab4[y * (Wn/2)] = make_float4(a0, mp0 - a0 * mI0, a1, mp1 - a1 * mI1);
            float4 qi0 = base[(y + r + 1) * Wn];
            float4 qi1 = base[(y + r + 1) * Wn + 1];
            float4 qo0 = base[(y - r) * Wn];
            float4 qo1 = base[(y - r) * Wn + 1];
            s0.x += qi0.x - qo0.x; s0.y += qi0.y - qo0.y;
            s0.z += qi0.z - qo0.z; s0.w += qi0.w - qo0.w;
            s1.x += qi1.x - qo1.x; s1.y += qi1.y - qo1.y;
            s1.z += qi1.z - qo1.z; s1.w += qi1.w - qo1.w;
        }
    } else {
        #pragma unroll 4
        for (int j = -r; j <= r; j++) {
            int yy = reflecti(y0 + j, Hn);
            float4 q0 = base[yy * Wn];
            float4 q1 = base[yy * Wn + 1];
            s0.x += q0.x; s0.y += q0.y; s0.z += q0.z; s0.w += q0.w;
            s1.x += q1.x; s1.y += q1.y; s1.z += q1.z; s1.w += q1.w;
        }
        #pragma unroll
        for (int y = y0; y < y0 + CH; y++) {
            float mI0  = s0.x * invk2, mp0  = s0.y * invk2;
            float mIp0 = s0.z * invk2, mII0 = s0.w * invk2;
            float a0 = (mIp0 - mI0 * mp0) / ((mII0 - mI0 * mI0) + 0.5f);
            float mI1  = s1.x * invk2, mp1  = s1.y * invk2;
            float mIp1 = s1.z * invk2, mII1 = s1.w * invk2;
            float a1 = (mIp1 - mI1 * mp1) / ((mII1 - mI1 * mI1) + 0.5f);
            gab4[y * (Wn/2)] = make_float4(a0, mp0 - a0 * mI0, a1, mp1 - a1 * mI1);
            int yi = reflecti(y + r + 1, Hn), yo = reflecti(y - r, Hn);
            float4 qi0 = base[yi * Wn];
            float4 qi1 = base[yi * Wn + 1];
            float4 qo0 = base[yo * Wn];
            float4 qo1 = base[yo * Wn + 1];
            s0.x += qi0.x - qo0.x; s0.y += qi0.y - qo0.y;
            s0.z += qi0.z - qo0.z; s0.w += qi0.w - qo0.w;
            s1.x += qi1.x - qo1.x; s1.y += qi1.y - qo1.y;
            s1.z += qi1.z - qo1.z; s1.w += qi1.w - qo1.w;
        }
    }
}

// ---------------- K3: horizontal box for (a,b) ----------------
__global__ void k_hbox2(const int* __restrict__ rp) {
    int r = clamp_r(rp[0]);
    __shared__ float2 P[Wn + 1];
    __shared__ float2 wsh[16];
    int x = threadIdx.x;
    int rowbase = blockIdx.x * Wn;
    float2 v = g_ab[rowbase + x];

    int lane = x & 31, wid = x >> 5;
    #pragma unroll
    for (int o = 1; o < 32; o <<= 1) {
        float ax = __shfl_up_sync(0xffffffffu, v.x, o);
        float ay = __shfl_up_sync(0xffffffffu, v.y, o);
        if (lane >= o) { v.x += ax; v.y += ay; }
    }
    if (lane == 31) wsh[wid] = v;
    __syncthreads();
    if (wid == 0) {
        float2 s = (lane < 16) ? wsh[lane] : make_float2(0.f,0.f);
        #pragma unroll
        for (int o = 1; o < 16; o <<= 1) {
            float ax = __shfl_up_sync(0xffffffffu, s.x, o);
            float ay = __shfl_up_sync(0xffffffffu, s.y, o);
            if (lane >= o) { s.x += ax; s.y += ay; }
        }
        if (lane < 16) wsh[lane] = s;
    }
    __syncthreads();
    if (wid > 0) { float2 off = wsh[wid - 1]; v.x += off.x; v.y += off.y; }
    P[x + 1] = v;
    if (x == 0) P[0] = make_float2(0.f,0.f);
    __syncthreads();

    int lo = x - r, hi = x + r;
    int ai = max(0, lo), bi = min(Wn - 1, hi);
    float2 Pb = P[bi + 1], Pa = P[ai];
    float2 s = make_float2(Pb.x - Pa.x, Pb.y - Pa.y);
    if (lo < 0)      { float2 q = P[-lo + 1], q0 = P[1];               s.x += q.x - q0.x; s.y += q.y - q0.y; }
    if (hi > Wn - 1) { float2 q = P[Wn - 1],  q0 = P[2*Wn - 2 - hi];   s.x += q.x - q0.x; s.y += q.y - q0.y; }
    g_i2[rowbase + x] = s;
}

// ---------------- K4: vertical box for (a,b), 2 cols/thread + t_final + J ----------------
__global__ void k_vbox2f(const float* __restrict__ img,
                         const float* __restrict__ Aa,
                         const int* __restrict__ rp,
                         float* __restrict__ out) {
    int r = clamp_r(rp[0]);
    int k = 2 * r + 1;
    float invk2 = 1.0f / ((float)(k * k));
    int gtid = blockIdx.x * blockDim.x + threadIdx.x;
    int px = gtid & 255;
    int t2 = gtid >> 8;
    int chunk = t2 & (Hn/CH - 1);
    int b = t2 / (Hn/CH);
    const float4* __restrict__ base = (const float4*)g_i2 + (b * HWn >> 1) + px;
    const float2* __restrict__ ip = (const float2*)img + (b * 3 * HWn >> 1) + px;
    float2* __restrict__ op = (float2*)out + (b * 3 * HWn >> 1) + px;
    const int RS = Wn / 2;          // row stride in float2/float4 pair units
    const int PS = HWn / 2;         // plane stride
    int y0 = chunk * CH;
    float A0 = Aa[b*3+0], A1 = Aa[b*3+1], A2 = Aa[b*3+2];
    float4 s = make_float4(0.f, 0.f, 0.f, 0.f);
    bool interior = (y0 - r >= 0) && (y0 + r + CH <= Hn - 1);
    if (interior) {
        #pragma unroll 4
        for (int j = -r; j <= r; j++) {
            float4 q = base[(y0 + j) * RS];
            s.x += q.x; s.y += q.y; s.z += q.z; s.w += q.w;
        }
    } else {
        #pragma unroll 4
        for (int j = -r; j <= r; j++) {
            float4 q = base[reflecti(y0 + j, Hn) * RS];
            s.x += q.x; s.y += q.y; s.z += q.z; s.w += q.w;
        }
    }
    #pragma unroll
    for (int y = y0; y < y0 + CH; y++) {
        float ma0 = s.x * invk2, mb0 = s.y * invk2;
        float ma1 = s.z * invk2, mb1 = s.w * invk2;
        float2 rv = ip[y * RS];
        float2 gv = ip[PS + y * RS];
        float2 bv = ip[2*PS + y * RS];
        float gray0 = 0.299f * rv.x + 0.587f * gv.x + 0.114f * bv.x;
        float gray1 = 0.299f * rv.y + 0.587f * gv.y + 0.114f * bv.y;
        float t0v = fminf(fmaxf(ma0 * gray0 + mb0, 0.1f), 1.0f);
        float t1v = fminf(fmaxf(ma1 * gray1 + mb1, 0.1f), 1.0f);
        float inv0 = 1.0f / (t0v + 1e-8f);
        float inv1 = 1.0f / (t1v + 1e-8f);
        float2 o0, o1, o2;
        o0.x = fminf(fmaxf((rv.x - A0) * inv0 + A0, 0.f), 1.f);
        o0.y = fminf(fmaxf((rv.y - A0) * inv1 + A0, 0.f), 1.f);
        o1.x = fminf(fmaxf((gv.x - A1) * inv0 + A1, 0.f), 1.f);
        o1.y = fminf(fmaxf((gv.y - A1) * inv1 + A1, 0.f), 1.f);
        o2.x = fminf(fmaxf((bv.x - A2) * inv0 + A2, 0.f), 1.f);
        o2.y = fminf(fmaxf((bv.y - A2) * inv1 + A2, 0.f), 1.f);
        op[y * RS] = o0;
        op[PS + y * RS] = o1;
        op[2*PS + y * RS] = o2;
        float4 qi, qo;
        if (interior) {
            qi = base[(y + r + 1) * RS];
            qo = base[(y - r) * RS];
        } else {
            qi = base[reflecti(y + r + 1, Hn) * RS];
            qo = base[reflecti(y - r, Hn) * RS];
        }
        s.x += qi.x - qo.x; s.y += qi.y - qo.y;
        s.z += qi.z - qo.z; s.w += qi.w - qo.w;
    }
}

// ---------------- histograms & selection (exact radix select on float bits) ----------------
__global__ void k_hist1(const float* __restrict__ J) {
    __shared__ unsigned int h[4096];
    for (int i = threadIdx.x; i < 4096; i += 256) h[i] = 0u;
    __syncthreads();
    int ch = blockIdx.y;
    const float4* p = (const float4*)(J + ch * HWn + blockIdx.x * 8192);
    for (int i = threadIdx.x; i < 2048; i += 256) {
        float4 v = p[i];
        unsigned int b0 = __float_as_uint(v.x) >> 18;
        unsigned int b1 = __float_as_uint(v.y) >> 18;
        unsigned int b2 = __float_as_uint(v.z) >> 18;
        unsigned int b3 = __float_as_uint(v.w) >> 18;
        atomicAdd(&h[min(b0, 4095u)], 1u);
        atomicAdd(&h[min(b1, 4095u)], 1u);
        atomicAdd(&h[min(b2, 4095u)], 1u);
        atomicAdd(&h[min(b3, 4095u)], 1u);
    }
    __syncthreads();
    for (int i = threadIdx.x; i < 4096; i += 256)
        if (h[i]) atomicAdd(&g_h1[ch*4096 + i], h[i]);
}

__global__ void k_sel1(const float* __restrict__ Ll, const float* __restrict__ Lh) {
    __shared__ unsigned int hsh[4096];
    __shared__ unsigned int seg[256];
    int ch = blockIdx.x;
    // zero g_h2 for the next pass (2*4096 per channel)
    for (int i = 0; i < 32; i++)
        g_h2[ch*8192 + i*256 + threadIdx.x] = 0u;
    unsigned int ssum = 0u;
    for (int j = 0; j < 16; j++) {
        unsigned int vv = g_h1[ch*4096 + threadIdx.x*16 + j];
        hsh[threadIdx.x*16 + j] = vv;
        ssum += vv;
    }
    seg[threadIdx.x] = ssum;
    __syncthreads();
    if (threadIdx.x == 0) {
        int b = ch / 3;
        for (int w = 0; w < 2; w++) {
            float Lv = (w == 0) ? Ll[b] : Lh[b];
            float fr = (Lv / 100.0f) * 262144.0f;
            int rank = (int)fr;
            if (rank < 0) rank = 0;
            if (rank > HWn - 1) rank = HWn - 1;
            unsigned int cum = 0u;
            int sI = 0;
            while (sI < 255 && cum + seg[sI] <= (unsigned int)rank) { cum += seg[sI]; sI++; }
            int bin = sI * 16;
            while (bin < sI*16 + 15 && cum + hsh[bin] <= (unsigned int)rank) { cum += hsh[bin]; bin++; }
            g_t1[ch*2 + w] = bin;
            g_r1[ch*2 + w] = rank - (int)cum;
        }
    }
}

// second (final) hist pass: refine the next 12 bits for both targets at once
__global__ void k_hist2(const float* __restrict__ J) {
    __shared__ unsigned int h[8192];
    for (int i = threadIdx.x; i < 8192; i += 256) h[i] = 0u;
    __syncthreads();
    int ch = blockIdx.y;
    int ta = g_t1[ch*2], tb = g_t1[ch*2 + 1];
    const float4* p = (const float4*)(J + ch * HWn + blockIdx.x * 16384);
    for (int i = threadIdx.x; i < 4096; i += 256) {
        float4 v = p[i];
        unsigned int bb[4] = {__float_as_uint(v.x), __float_as_uint(v.y),
                              __float_as_uint(v.z), __float_as_uint(v.w)};
        #pragma unroll
        for (int j = 0; j < 4; j++) {
            int top = (int)(bb[j] >> 18);
            unsigned int mid = (bb[j] >> 6) & 4095u;
            if (top == ta) atomicAdd(&h[mid], 1u);
            if (top == tb) atomicAdd(&h[4096 + mid], 1u);
        }
    }
    __syncthreads();
    for (int i = threadIdx.x; i < 8192; i += 256)
        if (h[i]) atomicAdd(&g_h2[ch*8192 + i], h[i]);
}

// final select: reconstruct percentile value (low 6 mantissa bits zeroed; <=64 ULP error)
__global__ void k_sel2() {
    __shared__ unsigned int hsh[8192];
    __shared__ unsigned int seg[512];
    int ch = blockIdx.x;
    for (int w = 0; w < 2; w++) {
        unsigned int ssum = 0u;
        for (int j = 0; j < 16; j++) {
            unsigned int vv = g_h2[ch*8192 + w*4096 + threadIdx.x*16 + j];
            hsh[w*4096 + threadIdx.x*16 + j] = vv;
            ssum += vv;
        }
        seg[w*256 + threadIdx.x] = ssum;
    }
    __syncthreads();
    if (threadIdx.x == 0) {
        for (int w = 0; w < 2; w++) {
            int rem = g_r1[ch*2 + w];
            unsigned int cum = 0u;
            int sI = 0;
            while (sI < 255 && cum + seg[w*256 + sI] <= (unsigned int)rem) { cum += seg[w*256 + sI]; sI++; }
            int bin = sI * 16;
            while (bin < sI*16 + 15 && cum + hsh[w*4096 + bin] <= (unsigned int)rem) { cum += hsh[w*4096 + bin]; bin++; }
            unsigned int bits = ((unsigned int)g_t1[ch*2 + w] << 18) | ((unsigned int)bin << 6);
            float pv = __uint_as_float(bits);
            if (w == 0) g_pl[ch] = pv; else g_ph[ch] = pv;
        }
    }
}

// ---------------- final normalize (in place on d_out), float4 ----------------
__global__ void k_final(float* __restrict__ out) {
    int i = blockIdx.x * blockDim.x + threadIdx.x;   // float4 index
    if (i >= 3 * BHWn / 4) return;
    int ch = i >> 16;            // (i*4) >> 18
    float pl = g_pl[ch], ph = g_ph[ch];
    float inv = 1.0f / (ph - pl + 1e-8f);
    float4 v = ((float4*)out)[i];
    v.x = fminf(fmaxf((fminf(fmaxf(v.x, pl), ph) - pl) * inv, 0.f), 1.f);
    v.y = fminf(fmaxf((fminf(fmaxf(v.y, pl), ph) - pl) * inv, 0.f), 1.f);
    v.z = fminf(fmaxf((fminf(fmaxf(v.z, pl), ph) - pl) * inv, 0.f), 1.f);
    v.w = fminf(fmaxf((fminf(fmaxf(v.w, pl), ph) - pl) * inv, 0.f), 1.f);
    ((float4*)out)[i] = v;
}

// ---------------- launch ----------------
extern "C" void kernel_launch(void* const* d_in, const int* in_sizes, int n_in,
                              void* d_out, int out_size) {
    const float* img   = (const float*)d_in[0];
    const float* omega = (const float*)d_in[1];
    const float* A     = (const float*)d_in[2];
    const float* Ll    = (const float*)d_in[3];
    const float* Lh    = (const float*)d_in[4];
    const int*   rp    = (const int*)d_in[5];
    float* out = (float*)d_out;

    int nvthreads = Bn * (Wn/2) * (Hn/CH);   // 262144

    k_hbox4 <<<Bn*Hn, 512>>>(img, omega, A, rp);
    k_vbox4 <<<nvthreads/128, 128>>>(rp);
    k_hbox2 <<<Bn*Hn, 512>>>(rp);
    k_vbox2f<<<nvthreads/128, 128>>>(img, A, rp, out);
    k_hist1 <<<dim3(32, NCH), 256>>>(out);
    k_sel1  <<<NCH, 256>>>(Ll, Lh);
    k_hist2 <<<dim3(16, NCH), 256>>>(out);
    k_sel2  <<<NCH, 256>>>();
    k_final <<<(3*BHWn/4 + 255)/256, 256>>>(out);
}

// round 6
// speedup vs baseline: 2.3691x; 1.0616x over previous
#include <cuda_runtime.h>
#include <math.h>

#define Bn   8
#define Hn   512
#define Wn   512
#define HWn  (Hn*Wn)      // 262144 = 2^18
#define BHWn (Bn*HWn)     // 2097152
#define NCH  24           // B*3 channels for percentile
#define CH   8            // rows per thread in vertical kernels

// ---------------- scratch (static device globals; no allocation) ----------------
__device__ float4 g_i4[BHWn];    // H-pass sums of (gray, tg, gray*tg, gray*gray)
__device__ float2 g_ab[BHWn];    // (a, b) guided filter coefficients
__device__ float2 g_i2[BHWn];    // H-pass sums of (a, b)
__device__ unsigned int g_h1[NCH*4096];
__device__ unsigned int g_h2[NCH*2*4096];
__device__ int   g_t1[NCH*2];
__device__ int   g_r1[NCH*2];
__device__ float g_pl[NCH];
__device__ float g_ph[NCH];

__device__ __forceinline__ int reflecti(int i, int n) {
    if (i < 0) i = -i;
    if (i > n - 1) i = 2 * (n - 1) - i;
    return i;
}
__device__ __forceinline__ int clamp_r(int r) {
    if (r < 1) r = 1;
    if (r > 50) r = 50;
    return r;
}

// ---------------- K1: fused t0/gray/tg + horizontal box (4 planes) ----------------
__global__ void k_hbox4(const float* __restrict__ img,
                        const float* __restrict__ omega,
                        const float* __restrict__ Aa,
                        const int* __restrict__ rp) {
    int r = clamp_r(rp[0]);
    __shared__ float4 P[Wn + 1];
    __shared__ float4 wsh[16];
    __shared__ float t0s[Wn];
    int x = threadIdx.x;               // 512 threads
    int rowid = blockIdx.x;            // B*H rows
    int b = rowid >> 9, y = rowid & 511;
    int ys = (y == 0) ? 0 : y - 1;

    // zero g_h1 for the later hist pass (4096 blocks * 24 = 98304 entries)
    if (x < NCH) g_h1[rowid * NCH + x] = 0u;

    const float* ib = img + b * 3 * HWn;
    float a0 = Aa[b*3+0] + 1e-8f;
    float a1 = Aa[b*3+1] + 1e-8f;
    float a2 = Aa[b*3+2] + 1e-8f;
    float om = omega[b];

    float rv = ib[y*Wn + x];
    float gv = ib[HWn + y*Wn + x];
    float bv = ib[2*HWn + y*Wn + x];
    float t0y = 1.0f - om * fminf(fminf(rv/a0, gv/a1), bv/a2);
    float t0yv;
    if (ys == y) {
        t0yv = t0y;
    } else {
        float rs = ib[ys*Wn + x];
        float gs = ib[HWn + ys*Wn + x];
        float bs = ib[2*HWn + ys*Wn + x];
        t0yv = 1.0f - om * fminf(fminf(rs/a0, gs/a1), bs/a2);
    }
    t0s[x] = t0yv;
    float gray = 0.299f * rv + 0.587f * gv + 0.114f * bv;
    __syncthreads();

    float txv;
    if (x == 0) {
        txv = t0s[0];
    } else {
        float tp = t0s[x - 1];
        txv = tp * __expf(-fabsf(t0yv - tp));
    }
    float tgv = txv * __expf(-fabsf(t0y - t0yv));

    float4 v = make_float4(gray, tgv, gray * tgv, gray * gray);

    int lane = x & 31, wid = x >> 5;
    #pragma unroll
    for (int o = 1; o < 32; o <<= 1) {
        float ax = __shfl_up_sync(0xffffffffu, v.x, o);
        float ay = __shfl_up_sync(0xffffffffu, v.y, o);
        float az = __shfl_up_sync(0xffffffffu, v.z, o);
        float aw = __shfl_up_sync(0xffffffffu, v.w, o);
        if (lane >= o) { v.x += ax; v.y += ay; v.z += az; v.w += aw; }
    }
    if (lane == 31) wsh[wid] = v;
    __syncthreads();
    if (wid == 0) {
        float4 s = (lane < 16) ? wsh[lane] : make_float4(0.f,0.f,0.f,0.f);
        #pragma unroll
        for (int o = 1; o < 16; o <<= 1) {
            float ax = __shfl_up_sync(0xffffffffu, s.x, o);
            float ay = __shfl_up_sync(0xffffffffu, s.y, o);
            float az = __shfl_up_sync(0xffffffffu, s.z, o);
            float aw = __shfl_up_sync(0xffffffffu, s.w, o);
            if (lane >= o) { s.x += ax; s.y += ay; s.z += az; s.w += aw; }
        }
        if (lane < 16) wsh[lane] = s;
    }
    __syncthreads();
    if (wid > 0) {
        float4 off = wsh[wid - 1];
        v.x += off.x; v.y += off.y; v.z += off.z; v.w += off.w;
    }
    P[x + 1] = v;
    if (x == 0) P[0] = make_float4(0.f,0.f,0.f,0.f);
    __syncthreads();

    int lo = x - r, hi = x + r;
    int ai = max(0, lo), bi = min(Wn - 1, hi);
    float4 Pb = P[bi + 1], Pa = P[ai];
    float4 s = make_float4(Pb.x - Pa.x, Pb.y - Pa.y, Pb.z - Pa.z, Pb.w - Pa.w);
    if (lo < 0) {
        float4 q  = P[-lo + 1], q0 = P[1];
        s.x += q.x - q0.x; s.y += q.y - q0.y; s.z += q.z - q0.z; s.w += q.w - q0.w;
    }
    if (hi > Wn - 1) {
        float4 q  = P[Wn - 1], q0 = P[2 * Wn - 2 - hi];
        s.x += q.x - q0.x; s.y += q.y - q0.y; s.z += q.z - q0.z; s.w += q.w - q0.w;
    }
    g_i4[rowid * Wn + x] = s;
}

// ---------------- K2: vertical box (sliding), 1 column/thread + a,b ----------------
__global__ void k_vbox4(const int* __restrict__ rp) {
    int r = clamp_r(rp[0]);
    int k = 2 * r + 1;
    float invk2 = 1.0f / ((float)(k * k));
    int gtid = blockIdx.x * blockDim.x + threadIdx.x;  // 262144 total
    int x = gtid & (Wn - 1);
    int t2 = gtid >> 9;
    int chunk = t2 & (Hn/CH - 1);
    int b = t2 / (Hn/CH);
    const float4* __restrict__ base = g_i4 + b * HWn + x;
    float2* __restrict__ outp = g_ab + b * HWn + x;
    int y0 = chunk * CH;
    float4 s = make_float4(0.f,0.f,0.f,0.f);
    if (y0 - r >= 0 && y0 + r + CH <= Hn - 1) {
        #pragma unroll 4
        for (int j = -r; j <= r; j++) {
            float4 q = base[(y0 + j) * Wn];
            s.x += q.x; s.y += q.y; s.z += q.z; s.w += q.w;
        }
        #pragma unroll
        for (int y = y0; y < y0 + CH; y++) {
            float mI  = s.x * invk2, mp  = s.y * invk2;
            float mIp = s.z * invk2, mII = s.w * invk2;
            float a = (mIp - mI * mp) / ((mII - mI * mI) + 0.5f);
            outp[y * Wn] = make_float2(a, mp - a * mI);
            float4 qi = base[(y + r + 1) * Wn];
            float4 qo = base[(y - r) * Wn];
            s.x += qi.x - qo.x; s.y += qi.y - qo.y;
            s.z += qi.z - qo.z; s.w += qi.w - qo.w;
        }
    } else {
        #pragma unroll 4
        for (int j = -r; j <= r; j++) {
            float4 q = base[reflecti(y0 + j, Hn) * Wn];
            s.x += q.x; s.y += q.y; s.z += q.z; s.w += q.w;
        }
        #pragma unroll
        for (int y = y0; y < y0 + CH; y++) {
            float mI  = s.x * invk2, mp  = s.y * invk2;
            float mIp = s.z * invk2, mII = s.w * invk2;
            float a = (mIp - mI * mp) / ((mII - mI * mI) + 0.5f);
            outp[y * Wn] = make_float2(a, mp - a * mI);
            float4 qi = base[reflecti(y + r + 1, Hn) * Wn];
            float4 qo = base[reflecti(y - r, Hn) * Wn];
            s.x += qi.x - qo.x; s.y += qi.y - qo.y;
            s.z += qi.z - qo.z; s.w += qi.w - qo.w;
        }
    }
}

// ---------------- K3: horizontal box for (a,b) ----------------
__global__ void k_hbox2(const int* __restrict__ rp) {
    int r = clamp_r(rp[0]);
    __shared__ float2 P[Wn + 1];
    __shared__ float2 wsh[16];
    int x = threadIdx.x;
    int rowbase = blockIdx.x * Wn;
    float2 v = g_ab[rowbase + x];

    int lane = x & 31, wid = x >> 5;
    #pragma unroll
    for (int o = 1; o < 32; o <<= 1) {
        float ax = __shfl_up_sync(0xffffffffu, v.x, o);
        float ay = __shfl_up_sync(0xffffffffu, v.y, o);
        if (lane >= o) { v.x += ax; v.y += ay; }
    }
    if (lane == 31) wsh[wid] = v;
    __syncthreads();
    if (wid == 0) {
        float2 s = (lane < 16) ? wsh[lane] : make_float2(0.f,0.f);
        #pragma unroll
        for (int o = 1; o < 16; o <<= 1) {
            float ax = __shfl_up_sync(0xffffffffu, s.x, o);
            float ay = __shfl_up_sync(0xffffffffu, s.y, o);
            if (lane >= o) { s.x += ax; s.y += ay; }
        }
        if (lane < 16) wsh[lane] = s;
    }
    __syncthreads();
    if (wid > 0) { float2 off = wsh[wid - 1]; v.x += off.x; v.y += off.y; }
    P[x + 1] = v;
    if (x == 0) P[0] = make_float2(0.f,0.f);
    __syncthreads();

    int lo = x - r, hi = x + r;
    int ai = max(0, lo), bi = min(Wn - 1, hi);
    float2 Pb = P[bi + 1], Pa = P[ai];
    float2 s = make_float2(Pb.x - Pa.x, Pb.y - Pa.y);
    if (lo < 0)      { float2 q = P[-lo + 1], q0 = P[1];               s.x += q.x - q0.x; s.y += q.y - q0.y; }
    if (hi > Wn - 1) { float2 q = P[Wn - 1],  q0 = P[2*Wn - 2 - hi];   s.x += q.x - q0.x; s.y += q.y - q0.y; }
    g_i2[rowbase + x] = s;
}

// ---------------- K4: vertical box for (a,b), 1 col/thread + t_final + J ----------------
__global__ void k_vbox2f(const float* __restrict__ img,
                         const float* __restrict__ Aa,
                         const int* __restrict__ rp,
                         float* __restrict__ out) {
    int r = clamp_r(rp[0]);
    int k = 2 * r + 1;
    float invk2 = 1.0f / ((float)(k * k));
    int gtid = blockIdx.x * blockDim.x + threadIdx.x;
    int x = gtid & (Wn - 1);
    int t2 = gtid >> 9;
    int chunk = t2 & (Hn/CH - 1);
    int b = t2 / (Hn/CH);
    const float2* __restrict__ base = g_i2 + b * HWn + x;
    const float* __restrict__ i0 = img + b * 3 * HWn + x;
    float* __restrict__ o0 = out + b * 3 * HWn + x;
    int y0 = chunk * CH;
    float A0 = Aa[b*3+0], A1 = Aa[b*3+1], A2 = Aa[b*3+2];
    float2 s = make_float2(0.f, 0.f);
    bool interior = (y0 - r >= 0) && (y0 + r + CH <= Hn - 1);
    if (interior) {
        #pragma unroll 4
        for (int j = -r; j <= r; j++) {
            float2 q = base[(y0 + j) * Wn];
            s.x += q.x; s.y += q.y;
        }
    } else {
        #pragma unroll 4
        for (int j = -r; j <= r; j++) {
            float2 q = base[reflecti(y0 + j, Hn) * Wn];
            s.x += q.x; s.y += q.y;
        }
    }
    #pragma unroll
    for (int y = y0; y < y0 + CH; y++) {
        float ma = s.x * invk2, mb = s.y * invk2;
        float rv = i0[y*Wn], gv = i0[HWn + y*Wn], bv = i0[2*HWn + y*Wn];
        float gray = 0.299f * rv + 0.587f * gv + 0.114f * bv;
        float t = fminf(fmaxf(ma * gray + mb, 0.1f), 1.0f);
        float inv = 1.0f / (t + 1e-8f);
        o0[y*Wn]         = fminf(fmaxf((rv - A0) * inv + A0, 0.f), 1.f);
        o0[HWn + y*Wn]   = fminf(fmaxf((gv - A1) * inv + A1, 0.f), 1.f);
        o0[2*HWn + y*Wn] = fminf(fmaxf((bv - A2) * inv + A2, 0.f), 1.f);
        float2 qi, qo;
        if (interior) {
            qi = base[(y + r + 1) * Wn];
            qo = base[(y - r) * Wn];
        } else {
            qi = base[reflecti(y + r + 1, Hn) * Wn];
            qo = base[reflecti(y - r, Hn) * Wn];
        }
        s.x += qi.x - qo.x; s.y += qi.y - qo.y;
    }
}

// ---------------- histograms & selection (radix select on float bits) ----------------
__global__ void k_hist1(const float* __restrict__ J) {
    __shared__ unsigned int h[4096];
    for (int i = threadIdx.x; i < 4096; i += 256) h[i] = 0u;
    __syncthreads();
    int ch = blockIdx.y;
    const float4* p = (const float4*)(J + ch * HWn + blockIdx.x * 8192);
    for (int i = threadIdx.x; i < 2048; i += 256) {
        float4 v = p[i];
        unsigned int b0 = __float_as_uint(v.x) >> 18;
        unsigned int b1 = __float_as_uint(v.y) >> 18;
        unsigned int b2 = __float_as_uint(v.z) >> 18;
        unsigned int b3 = __float_as_uint(v.w) >> 18;
        atomicAdd(&h[min(b0, 4095u)], 1u);
        atomicAdd(&h[min(b1, 4095u)], 1u);
        atomicAdd(&h[min(b2, 4095u)], 1u);
        atomicAdd(&h[min(b3, 4095u)], 1u);
    }
    __syncthreads();
    for (int i = threadIdx.x; i < 4096; i += 256)
        if (h[i]) atomicAdd(&g_h1[ch*4096 + i], h[i]);
}

__global__ void k_sel1(const float* __restrict__ Ll, const float* __restrict__ Lh) {
    __shared__ unsigned int hsh[4096];
    __shared__ unsigned int seg[256];
    int ch = blockIdx.x;
    // zero g_h2 for the next pass (2*4096 per channel)
    for (int i = 0; i < 32; i++)
        g_h2[ch*8192 + i*256 + threadIdx.x] = 0u;
    unsigned int ssum = 0u;
    for (int j = 0; j < 16; j++) {
        unsigned int vv = g_h1[ch*4096 + threadIdx.x*16 + j];
        hsh[threadIdx.x*16 + j] = vv;
        ssum += vv;
    }
    seg[threadIdx.x] = ssum;
    __syncthreads();
    if (threadIdx.x == 0) {
        int b = ch / 3;
        for (int w = 0; w < 2; w++) {
            float Lv = (w == 0) ? Ll[b] : Lh[b];
            float fr = (Lv / 100.0f) * 262144.0f;
            int rank = (int)fr;
            if (rank < 0) rank = 0;
            if (rank > HWn - 1) rank = HWn - 1;
            unsigned int cum = 0u;
            int sI = 0;
            while (sI < 255 && cum + seg[sI] <= (unsigned int)rank) { cum += seg[sI]; sI++; }
            int bin = sI * 16;
            while (bin < sI*16 + 15 && cum + hsh[bin] <= (unsigned int)rank) { cum += hsh[bin]; bin++; }
            g_t1[ch*2 + w] = bin;
            g_r1[ch*2 + w] = rank - (int)cum;
        }
    }
}

// second (final) hist pass: refine the next 12 bits for both targets at once
__global__ void k_hist2(const float* __restrict__ J) {
    __shared__ unsigned int h[8192];
    for (int i = threadIdx.x; i < 8192; i += 256) h[i] = 0u;
    __syncthreads();
    int ch = blockIdx.y;
    int ta = g_t1[ch*2], tb = g_t1[ch*2 + 1];
    const float4* p = (const float4*)(J + ch * HWn + blockIdx.x * 16384);
    for (int i = threadIdx.x; i < 4096; i += 256) {
        float4 v = p[i];
        unsigned int bb[4] = {__float_as_uint(v.x), __float_as_uint(v.y),
                              __float_as_uint(v.z), __float_as_uint(v.w)};
        #pragma unroll
        for (int j = 0; j < 4; j++) {
            int top = (int)(bb[j] >> 18);
            unsigned int mid = (bb[j] >> 6) & 4095u;
            if (top == ta) atomicAdd(&h[mid], 1u);
            if (top == tb) atomicAdd(&h[4096 + mid], 1u);
        }
    }
    __syncthreads();
    for (int i = threadIdx.x; i < 8192; i += 256)
        if (h[i]) atomicAdd(&g_h2[ch*8192 + i], h[i]);
}

// final select: reconstruct percentile value (low 6 mantissa bits zeroed; <=64 ULP error)
__global__ void k_sel2() {
    __shared__ unsigned int hsh[8192];
    __shared__ unsigned int seg[512];
    int ch = blockIdx.x;
    for (int w = 0; w < 2; w++) {
        unsigned int ssum = 0u;
        for (int j = 0; j < 16; j++) {
            unsigned int vv = g_h2[ch*8192 + w*4096 + threadIdx.x*16 + j];
            hsh[w*4096 + threadIdx.x*16 + j] = vv;
            ssum += vv;
        }
        seg[w*256 + threadIdx.x] = ssum;
    }
    __syncthreads();
    if (threadIdx.x == 0) {
        for (int w = 0; w < 2; w++) {
            int rem = g_r1[ch*2 + w];
            unsigned int cum = 0u;
            int sI = 0;
            while (sI < 255 && cum + seg[w*256 + sI] <= (unsigned int)rem) { cum += seg[w*256 + sI]; sI++; }
            int bin = sI * 16;
            while (bin < sI*16 + 15 && cum + hsh[w*4096 + bin] <= (unsigned int)rem) { cum += hsh[w*4096 + bin]; bin++; }
            unsigned int bits = ((unsigned int)g_t1[ch*2 + w] << 18) | ((unsigned int)bin << 6);
            float pv = __uint_as_float(bits);
            if (w == 0) g_pl[ch] = pv; else g_ph[ch] = pv;
        }
    }
}

// ---------------- final normalize (in place on d_out), float4 ----------------
__global__ void k_final(float* __restrict__ out) {
    int i = blockIdx.x * blockDim.x + threadIdx.x;   // float4 index
    if (i >= 3 * BHWn / 4) return;
    int ch = i >> 16;            // (i*4) >> 18
    float pl = g_pl[ch], ph = g_ph[ch];
    float inv = 1.0f / (ph - pl + 1e-8f);
    float4 v = ((float4*)out)[i];
    v.x = fminf(fmaxf((fminf(fmaxf(v.x, pl), ph) - pl) * inv, 0.f), 1.f);
    v.y = fminf(fmaxf((fminf(fmaxf(v.y, pl), ph) - pl) * inv, 0.f), 1.f);
    v.z = fminf(fmaxf((fminf(fmaxf(v.z, pl), ph) - pl) * inv, 0.f), 1.f);
    v.w = fminf(fmaxf((fminf(fmaxf(v.w, pl), ph) - pl) * inv, 0.f), 1.f);
    ((float4*)out)[i] = v;
}

// ---------------- launch ----------------
extern "C" void kernel_launch(void* const* d_in, const int* in_sizes, int n_in,
                              void* d_out, int out_size) {
    const float* img   = (const float*)d_in[0];
    const float* omega = (const float*)d_in[1];
    const float* A     = (const float*)d_in[2];
    const float* Ll    = (const float*)d_in[3];
    const float* Lh    = (const float*)d_in[4];
    const int*   rp    = (const int*)d_in[5];
    float* out = (float*)d_out;

    int nvthreads = Bn * Wn * (Hn/CH);   // 262144

    k_hbox4 <<<Bn*Hn, 512>>>(img, omega, A, rp);
    k_vbox4 <<<nvthreads/128, 128>>>(rp);
    k_hbox2 <<<Bn*Hn, 512>>>(rp);
    k_vbox2f<<<nvthreads/128, 128>>>(img, A, rp, out);
    k_hist1 <<<dim3(32, NCH), 256>>>(out);
    k_sel1  <<<NCH, 256>>>(Ll, Lh);
    k_hist2 <<<dim3(16, NCH), 256>>>(out);
    k_sel2  <<<NCH, 256>>>();
    k_final <<<(3*BHWn/4 + 255)/256, 256>>>(out);
}

// round 7
// speedup vs baseline: 2.4001x; 1.0131x over previous
#include <cuda_runtime.h>
#include <math.h>

#define Bn   8
#define Hn   512
#define Wn   512
#define HWn  (Hn*Wn)      // 262144 = 2^18
#define BHWn (Bn*HWn)     // 2097152
#define NCH  24           // B*3 channels for percentile
#define CH   8            // rows per thread in vertical kernels

// ---------------- scratch (static device globals; no allocation) ----------------
__device__ float4 g_i4[BHWn];    // H-pass sums of (gray, tg, gray*tg, gray*gray)
__device__ float2 g_ab[BHWn];    // (a, b) guided filter coefficients
__device__ float2 g_i2[BHWn];    // H-pass sums of (a, b)
__device__ unsigned int g_h1[NCH*4096];
__device__ unsigned int g_h2[NCH*2*4096];
__device__ int   g_t1[NCH*2];
__device__ int   g_r1[NCH*2];
__device__ float g_pl[NCH];
__device__ float g_ph[NCH];

__device__ __forceinline__ int reflecti(int i, int n) {
    if (i < 0) i = -i;
    if (i > n - 1) i = 2 * (n - 1) - i;
    return i;
}
__device__ __forceinline__ int clamp_r(int r) {
    if (r < 1) r = 1;
    if (r > 50) r = 50;
    return r;
}

// ---------------- K1: fused t0/gray/tg + horizontal box (4 planes) ----------------
__global__ void k_hbox4(const float* __restrict__ img,
                        const float* __restrict__ omega,
                        const float* __restrict__ Aa,
                        const int* __restrict__ rp) {
    int r = clamp_r(rp[0]);
    __shared__ float4 P[Wn + 1];
    __shared__ float4 wsh[16];
    __shared__ float t0s[Wn];
    int x = threadIdx.x;               // 512 threads
    int rowid = blockIdx.x;            // B*H rows
    int b = rowid >> 9, y = rowid & 511;
    int ys = (y == 0) ? 0 : y - 1;

    // zero g_h1 for the fused hist pass (4096 blocks * 24 = 98304 entries)
    if (x < NCH) g_h1[rowid * NCH + x] = 0u;

    const float* ib = img + b * 3 * HWn;
    float a0 = Aa[b*3+0] + 1e-8f;
    float a1 = Aa[b*3+1] + 1e-8f;
    float a2 = Aa[b*3+2] + 1e-8f;
    float om = omega[b];

    float rv = ib[y*Wn + x];
    float gv = ib[HWn + y*Wn + x];
    float bv = ib[2*HWn + y*Wn + x];
    float t0y = 1.0f - om * fminf(fminf(rv/a0, gv/a1), bv/a2);
    float t0yv;
    if (ys == y) {
        t0yv = t0y;
    } else {
        float rs = ib[ys*Wn + x];
        float gs = ib[HWn + ys*Wn + x];
        float bs = ib[2*HWn + ys*Wn + x];
        t0yv = 1.0f - om * fminf(fminf(rs/a0, gs/a1), bs/a2);
    }
    t0s[x] = t0yv;
    float gray = 0.299f * rv + 0.587f * gv + 0.114f * bv;
    __syncthreads();

    float txv;
    if (x == 0) {
        txv = t0s[0];
    } else {
        float tp = t0s[x - 1];
        txv = tp * __expf(-fabsf(t0yv - tp));
    }
    float tgv = txv * __expf(-fabsf(t0y - t0yv));

    float4 v = make_float4(gray, tgv, gray * tgv, gray * gray);

    int lane = x & 31, wid = x >> 5;
    #pragma unroll
    for (int o = 1; o < 32; o <<= 1) {
        float ax = __shfl_up_sync(0xffffffffu, v.x, o);
        float ay = __shfl_up_sync(0xffffffffu, v.y, o);
        float az = __shfl_up_sync(0xffffffffu, v.z, o);
        float aw = __shfl_up_sync(0xffffffffu, v.w, o);
        if (lane >= o) { v.x += ax; v.y += ay; v.z += az; v.w += aw; }
    }
    if (lane == 31) wsh[wid] = v;
    __syncthreads();
    if (wid == 0) {
        float4 s = (lane < 16) ? wsh[lane] : make_float4(0.f,0.f,0.f,0.f);
        #pragma unroll
        for (int o = 1; o < 16; o <<= 1) {
            float ax = __shfl_up_sync(0xffffffffu, s.x, o);
            float ay = __shfl_up_sync(0xffffffffu, s.y, o);
            float az = __shfl_up_sync(0xffffffffu, s.z, o);
            float aw = __shfl_up_sync(0xffffffffu, s.w, o);
            if (lane >= o) { s.x += ax; s.y += ay; s.z += az; s.w += aw; }
        }
        if (lane < 16) wsh[lane] = s;
    }
    __syncthreads();
    if (wid > 0) {
        float4 off = wsh[wid - 1];
        v.x += off.x; v.y += off.y; v.z += off.z; v.w += off.w;
    }
    P[x + 1] = v;
    if (x == 0) P[0] = make_float4(0.f,0.f,0.f,0.f);
    __syncthreads();

    int lo = x - r, hi = x + r;
    int ai = max(0, lo), bi = min(Wn - 1, hi);
    float4 Pb = P[bi + 1], Pa = P[ai];
    float4 s = make_float4(Pb.x - Pa.x, Pb.y - Pa.y, Pb.z - Pa.z, Pb.w - Pa.w);
    if (lo < 0) {
        float4 q  = P[-lo + 1], q0 = P[1];
        s.x += q.x - q0.x; s.y += q.y - q0.y; s.z += q.z - q0.z; s.w += q.w - q0.w;
    }
    if (hi > Wn - 1) {
        float4 q  = P[Wn - 1], q0 = P[2 * Wn - 2 - hi];
        s.x += q.x - q0.x; s.y += q.y - q0.y; s.z += q.z - q0.z; s.w += q.w - q0.w;
    }
    g_i4[rowid * Wn + x] = s;
}

// ---------------- K2: vertical box (sliding), 2 columns/thread + a,b ----------------
__global__ void k_vbox4(const int* __restrict__ rp) {
    int r = clamp_r(rp[0]);
    int k = 2 * r + 1;
    float invk2 = 1.0f / ((float)(k * k));
    int gtid = blockIdx.x * blockDim.x + threadIdx.x;  // 131072 total
    int px = gtid & 255;                // column pair 0..255
    int t2 = gtid >> 8;
    int chunk = t2 & (Hn/CH - 1);
    int b = t2 / (Hn/CH);
    const float4* __restrict__ base = g_i4 + b * HWn + px * 2;
    float4* __restrict__ gab4 = (float4*)g_ab + (b * HWn >> 1) + px;
    int y0 = chunk * CH;
    float4 s0 = make_float4(0.f,0.f,0.f,0.f);
    float4 s1 = make_float4(0.f,0.f,0.f,0.f);
    if (y0 - r >= 0 && y0 + r + CH <= Hn - 1) {
        #pragma unroll 4
        for (int j = -r; j <= r; j++) {
            float4 q0 = base[(y0 + j) * Wn];
            float4 q1 = base[(y0 + j) * Wn + 1];
            s0.x += q0.x; s0.y += q0.y; s0.z += q0.z; s0.w += q0.w;
            s1.x += q1.x; s1.y += q1.y; s1.z += q1.z; s1.w += q1.w;
        }
        #pragma unroll
        for (int y = y0; y < y0 + CH; y++) {
            float mI0  = s0.x * invk2, mp0  = s0.y * invk2;
            float mIp0 = s0.z * invk2, mII0 = s0.w * invk2;
            float a0 = (mIp0 - mI0 * mp0) / ((mII0 - mI0 * mI0) + 0.5f);
            float mI1  = s1.x * invk2, mp1  = s1.y * invk2;
            float mIp1 = s1.z * invk2, mII1 = s1.w * invk2;
            float a1 = (mIp1 - mI1 * mp1) / ((mII1 - mI1 * mI1) + 0.5f);
            gab4[y * (Wn/2)] = make_float4(a0, mp0 - a0 * mI0, a1, mp1 - a1 * mI1);
            float4 qi0 = base[(y + r + 1) * Wn];
            float4 qi1 = base[(y + r + 1) * Wn + 1];
            float4 qo0 = base[(y - r) * Wn];
            float4 qo1 = base[(y - r) * Wn + 1];
            s0.x += qi0.x - qo0.x; s0.y += qi0.y - qo0.y;
            s0.z += qi0.z - qo0.z; s0.w += qi0.w - qo0.w;
            s1.x += qi1.x - qo1.x; s1.y += qi1.y - qo1.y;
            s1.z += qi1.z - qo1.z; s1.w += qi1.w - qo1.w;
        }
    } else {
        #pragma unroll 4
        for (int j = -r; j <= r; j++) {
            int yy = reflecti(y0 + j, Hn);
            float4 q0 = base[yy * Wn];
            float4 q1 = base[yy * Wn + 1];
            s0.x += q0.x; s0.y += q0.y; s0.z += q0.z; s0.w += q0.w;
            s1.x += q1.x; s1.y += q1.y; s1.z += q1.z; s1.w += q1.w;
        }
        #pragma unroll
        for (int y = y0; y < y0 + CH; y++) {
            float mI0  = s0.x * invk2, mp0  = s0.y * invk2;
            float mIp0 = s0.z * invk2, mII0 = s0.w * invk2;
            float a0 = (mIp0 - mI0 * mp0) / ((mII0 - mI0 * mI0) + 0.5f);
            float mI1  = s1.x * invk2, mp1  = s1.y * invk2;
            float mIp1 = s1.z * invk2, mII1 = s1.w * invk2;
            float a1 = (mIp1 - mI1 * mp1) / ((mII1 - mI1 * mI1) + 0.5f);
            gab4[y * (Wn/2)] = make_float4(a0, mp0 - a0 * mI0, a1, mp1 - a1 * mI1);
            int yi = reflecti(y + r + 1, Hn), yo = reflecti(y - r, Hn);
            float4 qi0 = base[yi * Wn];
            float4 qi1 = base[yi * Wn + 1];
            float4 qo0 = base[yo * Wn];
            float4 qo1 = base[yo * Wn + 1];
            s0.x += qi0.x - qo0.x; s0.y += qi0.y - qo0.y;
            s0.z += qi0.z - qo0.z; s0.w += qi0.w - qo0.w;
            s1.x += qi1.x - qo1.x; s1.y += qi1.y - qo1.y;
            s1.z += qi1.z - qo1.z; s1.w += qi1.w - qo1.w;
        }
    }
}

// ---------------- K3: horizontal box for (a,b) ----------------
__global__ void k_hbox2(const int* __restrict__ rp) {
    int r = clamp_r(rp[0]);
    __shared__ float2 P[Wn + 1];
    __shared__ float2 wsh[16];
    int x = threadIdx.x;
    int rowbase = blockIdx.x * Wn;
    float2 v = g_ab[rowbase + x];

    int lane = x & 31, wid = x >> 5;
    #pragma unroll
    for (int o = 1; o < 32; o <<= 1) {
        float ax = __shfl_up_sync(0xffffffffu, v.x, o);
        float ay = __shfl_up_sync(0xffffffffu, v.y, o);
        if (lane >= o) { v.x += ax; v.y += ay; }
    }
    if (lane == 31) wsh[wid] = v;
    __syncthreads();
    if (wid == 0) {
        float2 s = (lane < 16) ? wsh[lane] : make_float2(0.f,0.f);
        #pragma unroll
        for (int o = 1; o < 16; o <<= 1) {
            float ax = __shfl_up_sync(0xffffffffu, s.x, o);
            float ay = __shfl_up_sync(0xffffffffu, s.y, o);
            if (lane >= o) { s.x += ax; s.y += ay; }
        }
        if (lane < 16) wsh[lane] = s;
    }
    __syncthreads();
    if (wid > 0) { float2 off = wsh[wid - 1]; v.x += off.x; v.y += off.y; }
    P[x + 1] = v;
    if (x == 0) P[0] = make_float2(0.f,0.f);
    __syncthreads();

    int lo = x - r, hi = x + r;
    int ai = max(0, lo), bi = min(Wn - 1, hi);
    float2 Pb = P[bi + 1], Pa = P[ai];
    float2 s = make_float2(Pb.x - Pa.x, Pb.y - Pa.y);
    if (lo < 0)      { float2 q = P[-lo + 1], q0 = P[1];               s.x += q.x - q0.x; s.y += q.y - q0.y; }
    if (hi > Wn - 1) { float2 q = P[Wn - 1],  q0 = P[2*Wn - 2 - hi];   s.x += q.x - q0.x; s.y += q.y - q0.y; }
    g_i2[rowbase + x] = s;
}

// ---------------- K4: vertical box (a,b) 2 cols/thread + t_final + J + fused hist1 ----------------
__global__ void k_vbox2f(const float* __restrict__ img,
                         const float* __restrict__ Aa,
                         const int* __restrict__ rp,
                         float* __restrict__ out) {
    // packed 16-bit histogram: 3 channels x 4096 bins -> 3*2048 uint32
    __shared__ unsigned int hcnt[3 * 2048];
    for (int i = threadIdx.x; i < 3 * 2048; i += 128) hcnt[i] = 0u;

    int r = clamp_r(rp[0]);
    int k = 2 * r + 1;
    float invk2 = 1.0f / ((float)(k * k));
    int gtid = blockIdx.x * blockDim.x + threadIdx.x;
    int px = gtid & 255;
    int t2 = gtid >> 8;
    int chunk = t2 & (Hn/CH - 1);
    int b = t2 / (Hn/CH);
    const float4* __restrict__ base = (const float4*)g_i2 + (b * HWn >> 1) + px;
    const float2* __restrict__ ip = (const float2*)img + (b * 3 * HWn >> 1) + px;
    float2* __restrict__ op = (float2*)out + (b * 3 * HWn >> 1) + px;
    const int RS = Wn / 2;
    const int PS = HWn / 2;
    int y0 = chunk * CH;
    float A0 = Aa[b*3+0], A1 = Aa[b*3+1], A2 = Aa[b*3+2];
    float4 s = make_float4(0.f, 0.f, 0.f, 0.f);
    bool interior = (y0 - r >= 0) && (y0 + r + CH <= Hn - 1);
    if (interior) {
        #pragma unroll 4
        for (int j = -r; j <= r; j++) {
            float4 q = base[(y0 + j) * RS];
            s.x += q.x; s.y += q.y; s.z += q.z; s.w += q.w;
        }
    } else {
        #pragma unroll 4
        for (int j = -r; j <= r; j++) {
            float4 q = base[reflecti(y0 + j, Hn) * RS];
            s.x += q.x; s.y += q.y; s.z += q.z; s.w += q.w;
        }
    }
    __syncthreads();   // hcnt zeroed before use
    #pragma unroll
    for (int y = y0; y < y0 + CH; y++) {
        float ma0 = s.x * invk2, mb0 = s.y * invk2;
        float ma1 = s.z * invk2, mb1 = s.w * invk2;
        float2 rv = ip[y * RS];
        float2 gv = ip[PS + y * RS];
        float2 bv = ip[2*PS + y * RS];
        float gray0 = 0.299f * rv.x + 0.587f * gv.x + 0.114f * bv.x;
        float gray1 = 0.299f * rv.y + 0.587f * gv.y + 0.114f * bv.y;
        float t0v = fminf(fmaxf(ma0 * gray0 + mb0, 0.1f), 1.0f);
        float t1v = fminf(fmaxf(ma1 * gray1 + mb1, 0.1f), 1.0f);
        float inv0 = 1.0f / (t0v + 1e-8f);
        float inv1 = 1.0f / (t1v + 1e-8f);
        float2 o0, o1, o2;
        o0.x = fminf(fmaxf((rv.x - A0) * inv0 + A0, 0.f), 1.f);
        o0.y = fminf(fmaxf((rv.y - A0) * inv1 + A0, 0.f), 1.f);
        o1.x = fminf(fmaxf((gv.x - A1) * inv0 + A1, 0.f), 1.f);
        o1.y = fminf(fmaxf((gv.y - A1) * inv1 + A1, 0.f), 1.f);
        o2.x = fminf(fmaxf((bv.x - A2) * inv0 + A2, 0.f), 1.f);
        o2.y = fminf(fmaxf((bv.y - A2) * inv1 + A2, 0.f), 1.f);
        op[y * RS] = o0;
        op[PS + y * RS] = o1;
        op[2*PS + y * RS] = o2;
        // fused hist1: bin the 6 J values (packed 16-bit counters)
        {
            unsigned int bin;
            bin = __float_as_uint(o0.x) >> 18; atomicAdd(&hcnt[(bin >> 1)], 1u << ((bin & 1) * 16));
            bin = __float_as_uint(o0.y) >> 18; atomicAdd(&hcnt[(bin >> 1)], 1u << ((bin & 1) * 16));
            bin = __float_as_uint(o1.x) >> 18; atomicAdd(&hcnt[2048 + (bin >> 1)], 1u << ((bin & 1) * 16));
            bin = __float_as_uint(o1.y) >> 18; atomicAdd(&hcnt[2048 + (bin >> 1)], 1u << ((bin & 1) * 16));
            bin = __float_as_uint(o2.x) >> 18; atomicAdd(&hcnt[4096 + (bin >> 1)], 1u << ((bin & 1) * 16));
            bin = __float_as_uint(o2.y) >> 18; atomicAdd(&hcnt[4096 + (bin >> 1)], 1u << ((bin & 1) * 16));
        }
        float4 qi, qo;
        if (interior) {
            qi = base[(y + r + 1) * RS];
            qo = base[(y - r) * RS];
        } else {
            qi = base[reflecti(y + r + 1, Hn) * RS];
            qo = base[reflecti(y - r, Hn) * RS];
        }
        s.x += qi.x - qo.x; s.y += qi.y - qo.y;
        s.z += qi.z - qo.z; s.w += qi.w - qo.w;
    }
    __syncthreads();
    // flush histogram to global
    for (int i = threadIdx.x; i < 3 * 2048; i += 128) {
        unsigned int v = hcnt[i];
        if (v) {
            int c = i >> 11;
            int word = i & 2047;
            unsigned int lo = v & 0xFFFFu, hi = v >> 16;
            unsigned int* dst = &g_h1[(b * 3 + c) * 4096 + 2 * word];
            if (lo) atomicAdd(dst, lo);
            if (hi) atomicAdd(dst + 1, hi);
        }
    }
}

// ---------------- selection pass 1 ----------------
__global__ void k_sel1(const float* __restrict__ Ll, const float* __restrict__ Lh) {
    __shared__ unsigned int hsh[4096];
    __shared__ unsigned int seg[256];
    int ch = blockIdx.x;
    // zero g_h2 for the next pass (2*4096 per channel)
    for (int i = 0; i < 32; i++)
        g_h2[ch*8192 + i*256 + threadIdx.x] = 0u;
    unsigned int ssum = 0u;
    for (int j = 0; j < 16; j++) {
        unsigned int vv = g_h1[ch*4096 + threadIdx.x*16 + j];
        hsh[threadIdx.x*16 + j] = vv;
        ssum += vv;
    }
    seg[threadIdx.x] = ssum;
    __syncthreads();
    if (threadIdx.x == 0) {
        int b = ch / 3;
        for (int w = 0; w < 2; w++) {
            float Lv = (w == 0) ? Ll[b] : Lh[b];
            float fr = (Lv / 100.0f) * 262144.0f;
            int rank = (int)fr;
            if (rank < 0) rank = 0;
            if (rank > HWn - 1) rank = HWn - 1;
            unsigned int cum = 0u;
            int sI = 0;
            while (sI < 255 && cum + seg[sI] <= (unsigned int)rank) { cum += seg[sI]; sI++; }
            int bin = sI * 16;
            while (bin < sI*16 + 15 && cum + hsh[bin] <= (unsigned int)rank) { cum += hsh[bin]; bin++; }
            g_t1[ch*2 + w] = bin;
            g_r1[ch*2 + w] = rank - (int)cum;
        }
    }
}

// second (final) hist pass: refine the next 12 bits for both targets at once
__global__ void k_hist2(const float* __restrict__ J) {
    __shared__ unsigned int h[8192];
    for (int i = threadIdx.x; i < 8192; i += 256) h[i] = 0u;
    __syncthreads();
    int ch = blockIdx.y;
    int ta = g_t1[ch*2], tb = g_t1[ch*2 + 1];
    const float4* p = (const float4*)(J + ch * HWn + blockIdx.x * 16384);
    for (int i = threadIdx.x; i < 4096; i += 256) {
        float4 v = p[i];
        unsigned int bb[4] = {__float_as_uint(v.x), __float_as_uint(v.y),
                              __float_as_uint(v.z), __float_as_uint(v.w)};
        #pragma unroll
        for (int j = 0; j < 4; j++) {
            int top = (int)(bb[j] >> 18);
            unsigned int mid = (bb[j] >> 6) & 4095u;
            if (top == ta) atomicAdd(&h[mid], 1u);
            if (top == tb) atomicAdd(&h[4096 + mid], 1u);
        }
    }
    __syncthreads();
    for (int i = threadIdx.x; i < 8192; i += 256)
        if (h[i]) atomicAdd(&g_h2[ch*8192 + i], h[i]);
}

// final select: reconstruct percentile value (low 6 mantissa bits zeroed; <=64 ULP error)
__global__ void k_sel2() {
    __shared__ unsigned int hsh[8192];
    __shared__ unsigned int seg[512];
    int ch = blockIdx.x;
    for (int w = 0; w < 2; w++) {
        unsigned int ssum = 0u;
        for (int j = 0; j < 16; j++) {
            unsigned int vv = g_h2[ch*8192 + w*4096 + threadIdx.x*16 + j];
            hsh[w*4096 + threadIdx.x*16 + j] = vv;
            ssum += vv;
        }
        seg[w*256 + threadIdx.x] = ssum;
    }
    __syncthreads();
    if (threadIdx.x == 0) {
        for (int w = 0; w < 2; w++) {
            int rem = g_r1[ch*2 + w];
            unsigned int cum = 0u;
            int sI = 0;
            while (sI < 255 && cum + seg[w*256 + sI] <= (unsigned int)rem) { cum += seg[w*256 + sI]; sI++; }
            int bin = sI * 16;
            while (bin < sI*16 + 15 && cum + hsh[w*4096 + bin] <= (unsigned int)rem) { cum += hsh[w*4096 + bin]; bin++; }
            unsigned int bits = ((unsigned int)g_t1[ch*2 + w] << 18) | ((unsigned int)bin << 6);
            float pv = __uint_as_float(bits);
            if (w == 0) g_pl[ch] = pv; else g_ph[ch] = pv;
        }
    }
}

// ---------------- final normalize (in place on d_out), float4 ----------------
__global__ void k_final(float* __restrict__ out) {
    int i = blockIdx.x * blockDim.x + threadIdx.x;   // float4 index
    if (i >= 3 * BHWn / 4) return;
    int ch = i >> 16;            // (i*4) >> 18
    float pl = g_pl[ch], ph = g_ph[ch];
    float inv = 1.0f / (ph - pl + 1e-8f);
    float4 v = ((float4*)out)[i];
    v.x = fminf(fmaxf((fminf(fmaxf(v.x, pl), ph) - pl) * inv, 0.f), 1.f);
    v.y = fminf(fmaxf((fminf(fmaxf(v.y, pl), ph) - pl) * inv, 0.f), 1.f);
    v.z = fminf(fmaxf((fminf(fmaxf(v.z, pl), ph) - pl) * inv, 0.f), 1.f);
    v.w = fminf(fmaxf((fminf(fmaxf(v.w, pl), ph) - pl) * inv, 0.f), 1.f);
    ((float4*)out)[i] = v;
}

// ---------------- launch ----------------
extern "C" void kernel_launch(void* const* d_in, const int* in_sizes, int n_in,
                              void* d_out, int out_size) {
    const float* img   = (const float*)d_in[0];
    const float* omega = (const float*)d_in[1];
    const float* A     = (const float*)d_in[2];
    const float* Ll    = (const float*)d_in[3];
    const float* Lh    = (const float*)d_in[4];
    const int*   rp    = (const int*)d_in[5];
    float* out = (float*)d_out;

    int nvthreads = Bn * (Wn/2) * (Hn/CH);   // 131072

    k_hbox4 <<<Bn*Hn, 512>>>(img, omega, A, rp);
    k_vbox4 <<<nvthreads/128, 128>>>(rp);
    k_hbox2 <<<Bn*Hn, 512>>>(rp);
    k_vbox2f<<<nvthreads/128, 128>>>(img, A, rp, out);
    k_sel1  <<<NCH, 256>>>(Ll, Lh);
    k_hist2 <<<dim3(16, NCH), 256>>>(out);
    k_sel2  <<<NCH, 256>>>();
    k_final <<<(3*BHWn/4 + 255)/256, 256>>>(out);
}

// round 8
// speedup vs baseline: 2.4676x; 1.0282x over previous
#include <cuda_runtime.h>
#include <math.h>

#define Bn   8
#define Hn   512
#define Wn   512
#define HWn  (Hn*Wn)      // 262144 = 2^18
#define BHWn (Bn*HWn)     // 2097152
#define NCH  24           // B*3 channels for percentile
#define CH   8            // rows per thread in vertical kernels

// ---------------- scratch (static device globals; no allocation) ----------------
__device__ float4 g_i4[BHWn];    // H-pass sums of (gray, tg, gray*tg, gray*gray)
__device__ float2 g_ab[BHWn];    // (a, b) guided filter coefficients
__device__ float2 g_i2[BHWn];    // H-pass sums of (a, b)
__device__ unsigned int g_h1[NCH*4096];
__device__ unsigned int g_h2[NCH*2*4096];
__device__ int   g_t1[NCH*2];
__device__ int   g_r1[NCH*2];
__device__ float g_pl[NCH];
__device__ float g_ph[NCH];

__device__ __forceinline__ int reflecti(int i, int n) {
    if (i < 0) i = -i;
    if (i > n - 1) i = 2 * (n - 1) - i;
    return i;
}
__device__ __forceinline__ int clamp_r(int r) {
    if (r < 1) r = 1;
    if (r > 50) r = 50;
    return r;
}

// ---------------- K1: fused t0/gray/tg + horizontal box (4 planes) ----------------
__global__ void k_hbox4(const float* __restrict__ img,
                        const float* __restrict__ omega,
                        const float* __restrict__ Aa,
                        const int* __restrict__ rp) {
    int r = clamp_r(rp[0]);
    __shared__ float4 P[Wn + 1];
    __shared__ float4 wsh[16];
    __shared__ float t0s[Wn];
    int x = threadIdx.x;               // 512 threads
    int rowid = blockIdx.x;            // B*H rows
    int b = rowid >> 9, y = rowid & 511;
    int ys = (y == 0) ? 0 : y - 1;

    // zero g_h1 for the hist pass (4096 blocks * 24 = 98304 entries)
    if (x < NCH) g_h1[rowid * NCH + x] = 0u;

    const float* ib = img + b * 3 * HWn;
    float a0 = Aa[b*3+0] + 1e-8f;
    float a1 = Aa[b*3+1] + 1e-8f;
    float a2 = Aa[b*3+2] + 1e-8f;
    float om = omega[b];

    float rv = ib[y*Wn + x];
    float gv = ib[HWn + y*Wn + x];
    float bv = ib[2*HWn + y*Wn + x];
    float t0y = 1.0f - om * fminf(fminf(rv/a0, gv/a1), bv/a2);
    float t0yv;
    if (ys == y) {
        t0yv = t0y;
    } else {
        float rs = ib[ys*Wn + x];
        float gs = ib[HWn + ys*Wn + x];
        float bs = ib[2*HWn + ys*Wn + x];
        t0yv = 1.0f - om * fminf(fminf(rs/a0, gs/a1), bs/a2);
    }
    t0s[x] = t0yv;
    float gray = 0.299f * rv + 0.587f * gv + 0.114f * bv;
    __syncthreads();

    float txv;
    if (x == 0) {
        txv = t0s[0];
    } else {
        float tp = t0s[x - 1];
        txv = tp * __expf(-fabsf(t0yv - tp));
    }
    float tgv = txv * __expf(-fabsf(t0y - t0yv));

    float4 v = make_float4(gray, tgv, gray * tgv, gray * gray);

    int lane = x & 31, wid = x >> 5;
    #pragma unroll
    for (int o = 1; o < 32; o <<= 1) {
        float ax = __shfl_up_sync(0xffffffffu, v.x, o);
        float ay = __shfl_up_sync(0xffffffffu, v.y, o);
        float az = __shfl_up_sync(0xffffffffu, v.z, o);
        float aw = __shfl_up_sync(0xffffffffu, v.w, o);
        if (lane >= o) { v.x += ax; v.y += ay; v.z += az; v.w += aw; }
    }
    if (lane == 31) wsh[wid] = v;
    __syncthreads();
    if (wid == 0) {
        float4 s = (lane < 16) ? wsh[lane] : make_float4(0.f,0.f,0.f,0.f);
        #pragma unroll
        for (int o = 1; o < 16; o <<= 1) {
            float ax = __shfl_up_sync(0xffffffffu, s.x, o);
            float ay = __shfl_up_sync(0xffffffffu, s.y, o);
            float az = __shfl_up_sync(0xffffffffu, s.z, o);
            float aw = __shfl_up_sync(0xffffffffu, s.w, o);
            if (lane >= o) { s.x += ax; s.y += ay; s.z += az; s.w += aw; }
        }
        if (lane < 16) wsh[lane] = s;
    }
    __syncthreads();
    if (wid > 0) {
        float4 off = wsh[wid - 1];
        v.x += off.x; v.y += off.y; v.z += off.z; v.w += off.w;
    }
    P[x + 1] = v;
    if (x == 0) P[0] = make_float4(0.f,0.f,0.f,0.f);
    __syncthreads();

    int lo = x - r, hi = x + r;
    int ai = max(0, lo), bi = min(Wn - 1, hi);
    float4 Pb = P[bi + 1], Pa = P[ai];
    float4 s = make_float4(Pb.x - Pa.x, Pb.y - Pa.y, Pb.z - Pa.z, Pb.w - Pa.w);
    if (lo < 0) {
        float4 q  = P[-lo + 1], q0 = P[1];
        s.x += q.x - q0.x; s.y += q.y - q0.y; s.z += q.z - q0.z; s.w += q.w - q0.w;
    }
    if (hi > Wn - 1) {
        float4 q  = P[Wn - 1], q0 = P[2 * Wn - 2 - hi];
        s.x += q.x - q0.x; s.y += q.y - q0.y; s.z += q.z - q0.z; s.w += q.w - q0.w;
    }
    g_i4[rowid * Wn + x] = s;
}

// ---------------- K2: vertical box (sliding), 2 columns/thread + a,b ----------------
__global__ void k_vbox4(const int* __restrict__ rp) {
    int r = clamp_r(rp[0]);
    int k = 2 * r + 1;
    float invk2 = 1.0f / ((float)(k * k));
    int gtid = blockIdx.x * blockDim.x + threadIdx.x;  // 131072 total
    int px = gtid & 255;                // column pair 0..255
    int t2 = gtid >> 8;
    int chunk = t2 & (Hn/CH - 1);
    int b = t2 / (Hn/CH);
    const float4* __restrict__ base = g_i4 + b * HWn + px * 2;
    float4* __restrict__ gab4 = (float4*)g_ab + (b * HWn >> 1) + px;
    int y0 = chunk * CH;
    float4 s0 = make_float4(0.f,0.f,0.f,0.f);
    float4 s1 = make_float4(0.f,0.f,0.f,0.f);
    if (y0 - r >= 0 && y0 + r + CH <= Hn - 1) {
        #pragma unroll 4
        for (int j = -r; j <= r; j++) {
            float4 q0 = base[(y0 + j) * Wn];
            float4 q1 = base[(y0 + j) * Wn + 1];
            s0.x += q0.x; s0.y += q0.y; s0.z += q0.z; s0.w += q0.w;
            s1.x += q1.x; s1.y += q1.y; s1.z += q1.z; s1.w += q1.w;
        }
        #pragma unroll
        for (int y = y0; y < y0 + CH; y++) {
            float mI0  = s0.x * invk2, mp0  = s0.y * invk2;
            float mIp0 = s0.z * invk2, mII0 = s0.w * invk2;
            float a0 = (mIp0 - mI0 * mp0) / ((mII0 - mI0 * mI0) + 0.5f);
            float mI1  = s1.x * invk2, mp1  = s1.y * invk2;
            float mIp1 = s1.z * invk2, mII1 = s1.w * invk2;
            float a1 = (mIp1 - mI1 * mp1) / ((mII1 - mI1 * mI1) + 0.5f);
            gab4[y * (Wn/2)] = make_float4(a0, mp0 - a0 * mI0, a1, mp1 - a1 * mI1);
            float4 qi0 = base[(y + r + 1) * Wn];
            float4 qi1 = base[(y + r + 1) * Wn + 1];
            float4 qo0 = base[(y - r) * Wn];
            float4 qo1 = base[(y - r) * Wn + 1];
            s0.x += qi0.x - qo0.x; s0.y += qi0.y - qo0.y;
            s0.z += qi0.z - qo0.z; s0.w += qi0.w - qo0.w;
            s1.x += qi1.x - qo1.x; s1.y += qi1.y - qo1.y;
            s1.z += qi1.z - qo1.z; s1.w += qi1.w - qo1.w;
        }
    } else {
        #pragma unroll 4
        for (int j = -r; j <= r; j++) {
            int yy = reflecti(y0 + j, Hn);
            float4 q0 = base[yy * Wn];
            float4 q1 = base[yy * Wn + 1];
            s0.x += q0.x; s0.y += q0.y; s0.z += q0.z; s0.w += q0.w;
            s1.x += q1.x; s1.y += q1.y; s1.z += q1.z; s1.w += q1.w;
        }
        #pragma unroll
        for (int y = y0; y < y0 + CH; y++) {
            float mI0  = s0.x * invk2, mp0  = s0.y * invk2;
            float mIp0 = s0.z * invk2, mII0 = s0.w * invk2;
            float a0 = (mIp0 - mI0 * mp0) / ((mII0 - mI0 * mI0) + 0.5f);
            float mI1  = s1.x * invk2, mp1  = s1.y * invk2;
            float mIp1 = s1.z * invk2, mII1 = s1.w * invk2;
            float a1 = (mIp1 - mI1 * mp1) / ((mII1 - mI1 * mI1) + 0.5f);
            gab4[y * (Wn/2)] = make_float4(a0, mp0 - a0 * mI0, a1, mp1 - a1 * mI1);
            int yi = reflecti(y + r + 1, Hn), yo = reflecti(y - r, Hn);
            float4 qi0 = base[yi * Wn];
            float4 qi1 = base[yi * Wn + 1];
            float4 qo0 = base[yo * Wn];
            float4 qo1 = base[yo * Wn + 1];
            s0.x += qi0.x - qo0.x; s0.y += qi0.y - qo0.y;
            s0.z += qi0.z - qo0.z; s0.w += qi0.w - qo0.w;
            s1.x += qi1.x - qo1.x; s1.y += qi1.y - qo1.y;
            s1.z += qi1.z - qo1.z; s1.w += qi1.w - qo1.w;
        }
    }
}

// ---------------- K3: horizontal box for (a,b) ----------------
__global__ void k_hbox2(const int* __restrict__ rp) {
    int r = clamp_r(rp[0]);
    __shared__ float2 P[Wn + 1];
    __shared__ float2 wsh[16];
    int x = threadIdx.x;
    int rowbase = blockIdx.x * Wn;
    float2 v = g_ab[rowbase + x];

    int lane = x & 31, wid = x >> 5;
    #pragma unroll
    for (int o = 1; o < 32; o <<= 1) {
        float ax = __shfl_up_sync(0xffffffffu, v.x, o);
        float ay = __shfl_up_sync(0xffffffffu, v.y, o);
        if (lane >= o) { v.x += ax; v.y += ay; }
    }
    if (lane == 31) wsh[wid] = v;
    __syncthreads();
    if (wid == 0) {
        float2 s = (lane < 16) ? wsh[lane] : make_float2(0.f,0.f);
        #pragma unroll
        for (int o = 1; o < 16; o <<= 1) {
            float ax = __shfl_up_sync(0xffffffffu, s.x, o);
            float ay = __shfl_up_sync(0xffffffffu, s.y, o);
            if (lane >= o) { s.x += ax; s.y += ay; }
        }
        if (lane < 16) wsh[lane] = s;
    }
    __syncthreads();
    if (wid > 0) { float2 off = wsh[wid - 1]; v.x += off.x; v.y += off.y; }
    P[x + 1] = v;
    if (x == 0) P[0] = make_float2(0.f,0.f);
    __syncthreads();

    int lo = x - r, hi = x + r;
    int ai = max(0, lo), bi = min(Wn - 1, hi);
    float2 Pb = P[bi + 1], Pa = P[ai];
    float2 s = make_float2(Pb.x - Pa.x, Pb.y - Pa.y);
    if (lo < 0)      { float2 q = P[-lo + 1], q0 = P[1];               s.x += q.x - q0.x; s.y += q.y - q0.y; }
    if (hi > Wn - 1) { float2 q = P[Wn - 1],  q0 = P[2*Wn - 2 - hi];   s.x += q.x - q0.x; s.y += q.y - q0.y; }
    g_i2[rowbase + x] = s;
}

// ---------------- K4: vertical box for (a,b), 2 cols/thread + t_final + J ----------------
__global__ void k_vbox2f(const float* __restrict__ img,
                         const float* __restrict__ Aa,
                         const int* __restrict__ rp,
                         float* __restrict__ out) {
    int r = clamp_r(rp[0]);
    int k = 2 * r + 1;
    float invk2 = 1.0f / ((float)(k * k));
    int gtid = blockIdx.x * blockDim.x + threadIdx.x;
    int px = gtid & 255;
    int t2 = gtid >> 8;
    int chunk = t2 & (Hn/CH - 1);
    int b = t2 / (Hn/CH);
    const float4* __restrict__ base = (const float4*)g_i2 + (b * HWn >> 1) + px;
    const float2* __restrict__ ip = (const float2*)img + (b * 3 * HWn >> 1) + px;
    float2* __restrict__ op = (float2*)out + (b * 3 * HWn >> 1) + px;
    const int RS = Wn / 2;          // row stride in float2/float4 pair units
    const int PS = HWn / 2;         // plane stride
    int y0 = chunk * CH;
    float A0 = Aa[b*3+0], A1 = Aa[b*3+1], A2 = Aa[b*3+2];
    float4 s = make_float4(0.f, 0.f, 0.f, 0.f);
    bool interior = (y0 - r >= 0) && (y0 + r + CH <= Hn - 1);
    if (interior) {
        #pragma unroll 4
        for (int j = -r; j <= r; j++) {
            float4 q = base[(y0 + j) * RS];
            s.x += q.x; s.y += q.y; s.z += q.z; s.w += q.w;
        }
    } else {
        #pragma unroll 4
        for (int j = -r; j <= r; j++) {
            float4 q = base[reflecti(y0 + j, Hn) * RS];
            s.x += q.x; s.y += q.y; s.z += q.z; s.w += q.w;
        }
    }
    #pragma unroll
    for (int y = y0; y < y0 + CH; y++) {
        float ma0 = s.x * invk2, mb0 = s.y * invk2;
        float ma1 = s.z * invk2, mb1 = s.w * invk2;
        float2 rv = ip[y * RS];
        float2 gv = ip[PS + y * RS];
        float2 bv = ip[2*PS + y * RS];
        float gray0 = 0.299f * rv.x + 0.587f * gv.x + 0.114f * bv.x;
        float gray1 = 0.299f * rv.y + 0.587f * gv.y + 0.114f * bv.y;
        float t0v = fminf(fmaxf(ma0 * gray0 + mb0, 0.1f), 1.0f);
        float t1v = fminf(fmaxf(ma1 * gray1 + mb1, 0.1f), 1.0f);
        float inv0 = 1.0f / (t0v + 1e-8f);
        float inv1 = 1.0f / (t1v + 1e-8f);
        float2 o0, o1, o2;
        o0.x = fminf(fmaxf((rv.x - A0) * inv0 + A0, 0.f), 1.f);
        o0.y = fminf(fmaxf((rv.y - A0) * inv1 + A0, 0.f), 1.f);
        o1.x = fminf(fmaxf((gv.x - A1) * inv0 + A1, 0.f), 1.f);
        o1.y = fminf(fmaxf((gv.y - A1) * inv1 + A1, 0.f), 1.f);
        o2.x = fminf(fmaxf((bv.x - A2) * inv0 + A2, 0.f), 1.f);
        o2.y = fminf(fmaxf((bv.y - A2) * inv1 + A2, 0.f), 1.f);
        op[y * RS] = o0;
        op[PS + y * RS] = o1;
        op[2*PS + y * RS] = o2;
        float4 qi, qo;
        if (interior) {
            qi = base[(y + r + 1) * RS];
            qo = base[(y - r) * RS];
        } else {
            qi = base[reflecti(y + r + 1, Hn) * RS];
            qo = base[reflecti(y - r, Hn) * RS];
        }
        s.x += qi.x - qo.x; s.y += qi.y - qo.y;
        s.z += qi.z - qo.z; s.w += qi.w - qo.w;
    }
}

// ---------------- hist pass 1 (top 12 bits of clipped J) ----------------
__global__ void k_hist1(const float* __restrict__ J) {
    __shared__ unsigned int h[4096];
    for (int i = threadIdx.x; i < 4096; i += 256) h[i] = 0u;
    __syncthreads();
    int ch = blockIdx.y;
    const float4* p = (const float4*)(J + ch * HWn + blockIdx.x * 8192);
    for (int i = threadIdx.x; i < 2048; i += 256) {
        float4 v = p[i];
        unsigned int b0 = __float_as_uint(v.x) >> 18;
        unsigned int b1 = __float_as_uint(v.y) >> 18;
        unsigned int b2 = __float_as_uint(v.z) >> 18;
        unsigned int b3 = __float_as_uint(v.w) >> 18;
        atomicAdd(&h[min(b0, 4095u)], 1u);
        atomicAdd(&h[min(b1, 4095u)], 1u);
        atomicAdd(&h[min(b2, 4095u)], 1u);
        atomicAdd(&h[min(b3, 4095u)], 1u);
    }
    __syncthreads();
    for (int i = threadIdx.x; i < 4096; i += 256)
        if (h[i]) atomicAdd(&g_h1[ch*4096 + i], h[i]);
}

// ---------------- selection pass 1 ----------------
__global__ void k_sel1(const float* __restrict__ Ll, const float* __restrict__ Lh) {
    __shared__ unsigned int hsh[4096];
    __shared__ unsigned int seg[256];
    int ch = blockIdx.x;
    // zero g_h2 for the next pass (2*4096 per channel)
    for (int i = 0; i < 32; i++)
        g_h2[ch*8192 + i*256 + threadIdx.x] = 0u;
    unsigned int ssum = 0u;
    for (int j = 0; j < 16; j++) {
        unsigned int vv = g_h1[ch*4096 + threadIdx.x*16 + j];
        hsh[threadIdx.x*16 + j] = vv;
        ssum += vv;
    }
    seg[threadIdx.x] = ssum;
    __syncthreads();
    if (threadIdx.x == 0) {
        int b = ch / 3;
        for (int w = 0; w < 2; w++) {
            float Lv = (w == 0) ? Ll[b] : Lh[b];
            float fr = (Lv / 100.0f) * 262144.0f;
            int rank = (int)fr;
            if (rank < 0) rank = 0;
            if (rank > HWn - 1) rank = HWn - 1;
            unsigned int cum = 0u;
            int sI = 0;
            while (sI < 255 && cum + seg[sI] <= (unsigned int)rank) { cum += seg[sI]; sI++; }
            int bin = sI * 16;
            while (bin < sI*16 + 15 && cum + hsh[bin] <= (unsigned int)rank) { cum += hsh[bin]; bin++; }
            g_t1[ch*2 + w] = bin;
            g_r1[ch*2 + w] = rank - (int)cum;
        }
    }
}

// second (final) hist pass: refine the next 12 bits for both targets at once
__global__ void k_hist2(const float* __restrict__ J) {
    __shared__ unsigned int h[8192];
    for (int i = threadIdx.x; i < 8192; i += 256) h[i] = 0u;
    __syncthreads();
    int ch = blockIdx.y;
    int ta = g_t1[ch*2], tb = g_t1[ch*2 + 1];
    const float4* p = (const float4*)(J + ch * HWn + blockIdx.x * 16384);
    for (int i = threadIdx.x; i < 4096; i += 256) {
        float4 v = p[i];
        unsigned int bb[4] = {__float_as_uint(v.x), __float_as_uint(v.y),
                              __float_as_uint(v.z), __float_as_uint(v.w)};
        #pragma unroll
        for (int j = 0; j < 4; j++) {
            int top = (int)(bb[j] >> 18);
            unsigned int mid = (bb[j] >> 6) & 4095u;
            if (top == ta) atomicAdd(&h[mid], 1u);
            if (top == tb) atomicAdd(&h[4096 + mid], 1u);
        }
    }
    __syncthreads();
    for (int i = threadIdx.x; i < 8192; i += 256)
        if (h[i]) atomicAdd(&g_h2[ch*8192 + i], h[i]);
}

// final select: reconstruct percentile value (low 6 mantissa bits zeroed; <=64 ULP error)
__global__ void k_sel2() {
    __shared__ unsigned int hsh[8192];
    __shared__ unsigned int seg[512];
    int ch = blockIdx.x;
    for (int w = 0; w < 2; w++) {
        unsigned int ssum = 0u;
        for (int j = 0; j < 16; j++) {
            unsigned int vv = g_h2[ch*8192 + w*4096 + threadIdx.x*16 + j];
            hsh[w*4096 + threadIdx.x*16 + j] = vv;
            ssum += vv;
        }
        seg[w*256 + threadIdx.x] = ssum;
    }
    __syncthreads();
    if (threadIdx.x == 0) {
        for (int w = 0; w < 2; w++) {
            int rem = g_r1[ch*2 + w];
            unsigned int cum = 0u;
            int sI = 0;
            while (sI < 255 && cum + seg[w*256 + sI] <= (unsigned int)rem) { cum += seg[w*256 + sI]; sI++; }
            int bin = sI * 16;
            while (bin < sI*16 + 15 && cum + hsh[w*4096 + bin] <= (unsigned int)rem) { cum += hsh[w*4096 + bin]; bin++; }
            unsigned int bits = ((unsigned int)g_t1[ch*2 + w] << 18) | ((unsigned int)bin << 6);
            float pv = __uint_as_float(bits);
            if (w == 0) g_pl[ch] = pv; else g_ph[ch] = pv;
        }
    }
}

// ---------------- final normalize (in place on d_out), float4 ----------------
__global__ void k_final(float* __restrict__ out) {
    int i = blockIdx.x * blockDim.x + threadIdx.x;   // float4 index
    if (i >= 3 * BHWn / 4) return;
    int ch = i >> 16;            // (i*4) >> 18
    float pl = g_pl[ch], ph = g_ph[ch];
    float inv = 1.0f / (ph - pl + 1e-8f);
    float4 v = ((float4*)out)[i];
    v.x = fminf(fmaxf((fminf(fmaxf(v.x, pl), ph) - pl) * inv, 0.f), 1.f);
    v.y = fminf(fmaxf((fminf(fmaxf(v.y, pl), ph) - pl) * inv, 0.f), 1.f);
    v.z = fminf(fmaxf((fminf(fmaxf(v.z, pl), ph) - pl) * inv, 0.f), 1.f);
    v.w = fminf(fmaxf((fminf(fmaxf(v.w, pl), ph) - pl) * inv, 0.f), 1.f);
    ((float4*)out)[i] = v;
}

// ---------------- launch ----------------
extern "C" void kernel_launch(void* const* d_in, const int* in_sizes, int n_in,
                              void* d_out, int out_size) {
    const float* img   = (const float*)d_in[0];
    const float* omega = (const float*)d_in[1];
    const float* A     = (const float*)d_in[2];
    const float* Ll    = (const float*)d_in[3];
    const float* Lh    = (const float*)d_in[4];
    const int*   rp    = (const int*)d_in[5];
    float* out = (float*)d_out;

    int nvthreads = Bn * (Wn/2) * (Hn/CH);   // 131072

    k_hbox4 <<<Bn*Hn, 512>>>(img, omega, A, rp);
    k_vbox4 <<<nvthreads/128, 128>>>(rp);
    k_hbox2 <<<Bn*Hn, 512>>>(rp);
    k_vbox2f<<<nvthreads/128, 128>>>(img, A, rp, out);
    k_hist1 <<<dim3(32, NCH), 256>>>(out);
    k_sel1  <<<NCH, 256>>>(Ll, Lh);
    k_hist2 <<<dim3(16, NCH), 256>>>(out);
    k_sel2  <<<NCH, 256>>>();
    k_final <<<(3*BHWn/4 + 255)/256, 256>>>(out);
}